// round 14
// baseline (speedup 1.0000x reference)
#include <cuda_runtime.h>
#include <cuda_fp16.h>
#include <cstdint>
#include <math.h>

// Problem dims
#define NB 2048
#define ND 1024
#define NH 1024
#define NZ 256
#define NE 64

// ---------------- scratch (static device globals; no allocation) ----------------
__device__ __align__(16) __half g_hcat[NB * (NZ + NH + ND)];  // [B,2304]; cols 256.. = [h0|x]
__device__ __align__(16) float  g_hgp[2 * NB * 4 * NZ];       // split-K partials
__device__ __align__(16) __half g_hhat1h[NB * NZ];            // [B,256]
__device__ __align__(16) __half g_z[NB * NZ];                 // z_b [B,256]
__device__ __align__(16) float  g_W4[2 * 256 * 4];            // colsums of zw_h/zw_x per gate
__device__ __align__(16) float  g_W4b[8];                     // per-gate zbias sums
__device__ __align__(16) float  g_dyhx[NB * 4];               // per-(b,gate) dyh*dyx
__device__ __align__(16) __half g_hwT[1024 * 2304];           // [N,K]
__device__ __align__(16) __half g_wT[4096 * 2048];            // [N,K]
__device__ __align__(16) __half g_zwT[256 * 256];             // zweight_b^T
__device__ __align__(16) __half g_dwT[4 * 1024 * 64];         // dw_b^T per gate
__device__ __align__(16) __half g_gates[NB * 4 * NH];         // fp16 gates

// fast activations
__device__ __forceinline__ float sigf(float v) {
    return __fdividef(1.f, 1.f + __expf(-v));
}
__device__ __forceinline__ float tanh_fast(float x) {
    return 1.f - __fdividef(2.f, __expf(2.f * x) + 1.f);
}

__device__ __forceinline__ uint32_t smem_u32(const void* p) {
    uint32_t a;
    asm("{ .reg .u64 t; cvta.to.shared.u64 t, %1; cvt.u32.u64 %0, t; }" : "=r"(a) : "l"(p));
    return a;
}
__device__ __forceinline__ void cpasync16(uint32_t saddr, const void* gaddr) {
    asm volatile("cp.async.cg.shared.global [%0], [%1], 16;" :: "r"(saddr), "l"(gaddr));
}
#define COMMIT() asm volatile("cp.async.commit_group;" ::: "memory")
#define WAITG0() asm volatile("cp.async.wait_group 0;" ::: "memory")
#define WAITG1() asm volatile("cp.async.wait_group 1;" ::: "memory")
#define WAITG2() asm volatile("cp.async.wait_group 2;" ::: "memory")

#define LDSM_X4(r, addr) \
    asm volatile("ldmatrix.sync.aligned.m8n8.x4.shared.b16 {%0,%1,%2,%3}, [%4];" \
        : "=r"((r)[0]), "=r"((r)[1]), "=r"((r)[2]), "=r"((r)[3]) : "r"(addr))

__device__ __forceinline__ void mma_f16(float* d, const uint32_t* a, const uint32_t* b) {
    asm volatile("mma.sync.aligned.m16n8k16.row.col.f32.f16.f16.f32 "
                 "{%0,%1,%2,%3}, {%4,%5,%6,%7}, {%8,%9}, {%0,%1,%2,%3};"
                 : "+f"(d[0]), "+f"(d[1]), "+f"(d[2]), "+f"(d[3])
                 : "r"(a[0]), "r"(a[1]), "r"(a[2]), "r"(a[3]), "r"(b[0]), "r"(b[1]));
}

__device__ __forceinline__ uint2 f4_to_h4(float4 v) {
    __half2 a = __floats2half2_rn(v.x, v.y);
    __half2 b = __floats2half2_rn(v.z, v.w);
    uint2 r;
    r.x = *reinterpret_cast<uint32_t*>(&a);
    r.y = *reinterpret_cast<uint32_t*>(&b);
    return r;
}

// ---------------- transpose helper (32x32 tile, f32 in -> f16 out [N,K]) ----------------
__device__ __forceinline__ void transpose_tile(const float* __restrict__ in,
                                               __half* __restrict__ out,
                                               int K, int N, int lt, float* tbuf) {
    float (*t)[33] = reinterpret_cast<float(*)[33]>(tbuf);
    const int ntx = N >> 5;
    const int tx = lt % ntx, ty = lt / ntx;
    const int lx = threadIdx.x & 31, ly = threadIdx.x >> 5;
#pragma unroll
    for (int j = 0; j < 4; j++) {
        int k = ly + j * 8;
        t[k][lx] = in[(size_t)(ty * 32 + k) * N + tx * 32 + lx];
    }
    __syncthreads();
#pragma unroll
    for (int j = 0; j < 4; j++) {
        int r = ly + j * 8;
        out[(size_t)(tx * 32 + r) * K + ty * 32 + lx] = __float2half_rn(t[lx][r]);
    }
}

// ---------------- prep (critical path): concat + hwT + zwT(z_b) + colsums ----------------
// blocks: [0,1024) concat | [1024,3328) hwT | [3328,3392) zwT_b | [3392,3394) colsums
__global__ __launch_bounds__(256)
void prep_main(const float4* __restrict__ x, const float4* __restrict__ h0,
               const float4* __restrict__ hhat0,
               const float* __restrict__ hw,
               const float* __restrict__ zh, const float* __restrict__ zx,
               const float* __restrict__ zb,
               const float* __restrict__ zbias_h, const float* __restrict__ zbias_x) {
    __shared__ float tbuf[32 * 33];
    if (blockIdx.x < 1024) {
        uint2* hc = reinterpret_cast<uint2*>(g_hcat);
        const int HC4 = (NZ + NH + ND) / 4;  // 576
        const int N1 = NB * HC4;
        const int stride = 1024 * 256;
        const int t0 = blockIdx.x * 256 + threadIdx.x;
        for (int i = t0; i < N1; i += stride) {
            int b = i / HC4;
            int c = i - b * HC4;
            float4 v;
            if (c < NZ / 4)                 v = hhat0[b * (NZ / 4) + c];
            else if (c < (NZ + NH) / 4)     v = h0[b * (NH / 4) + (c - NZ / 4)];
            else                            v = x[b * (ND / 4) + (c - (NZ + NH) / 4)];
            hc[i] = f4_to_h4(v);
        }
        return;
    }
    int b2 = blockIdx.x - 1024;
    if (b2 < 2304) {
        transpose_tile(hw, g_hwT, 2304, 1024, b2, tbuf);
    } else if (b2 < 2368) {
        transpose_tile(zb, g_zwT, 256, 256, b2 - 2304, tbuf);
    } else {
        // colsum blocks: per-k gate sums of zw_h / zw_x + per-gate zbias sums
        int sel = b2 - 2368;                 // 0 = h, 1 = x
        const float* src = sel ? zx : zh;
        int k = threadIdx.x;                 // 0..255
        float s[4] = {0.f, 0.f, 0.f, 0.f};
        for (int e = 0; e < 256; e++) s[e >> 6] += src[k * 256 + e];
#pragma unroll
        for (int g = 0; g < 4; g++) g_W4[sel * 1024 + k * 4 + g] = s[g];
        if (k < 4) {
            const float* bsrc = sel ? zbias_x : zbias_h;
            float sb = 0.f;
            for (int e = 0; e < 64; e++) sb += bsrc[k * 64 + e];
            g_W4b[sel * 4 + k] = sb;
        }
    }
}

// ---------------- prep (side branch): wT + dwT(b) transposes ----------------
__global__ __launch_bounds__(256)
void prep_side(const float* __restrict__ w, const float* __restrict__ db) {
    __shared__ float tbuf[32 * 33];
    int b2 = blockIdx.x;
    if (b2 < 8192) {
        transpose_tile(w, g_wT, 2048, 4096, b2, tbuf);
    } else {
        int g = (b2 - 8192) >> 6;      // 0..3
        transpose_tile(db + (size_t)g * 64 * 1024, g_dwT + (size_t)g * 1024 * 64,
                       64, 1024, (b2 - 8192) & 63, tbuf);
    }
}

// ---------------- shared GEMM geometry ----------------
#define SLDH 72                       // smem row stride in halfs (144B)
#define TILE_B (128 * SLDH * 2)       // 18432 bytes per operand tile
#define STAGE_B (2 * TILE_B)          // 36864 per stage
#define SMEM_TOT (3 * STAGE_B)        // 110592, 3 stages

// ---------------- fp16 GEMM core: 128x128 tile, BK=64, 3-stage ----------------
__device__ __forceinline__ void gemm_core(
    const __half* __restrict__ A, int lda,
    const __half* __restrict__ Wt, int ldw,
    void* __restrict__ Cv, int ldc, int K,
    const float* __restrict__ bias, int out_half,
    int bM, int bN) {
    extern __shared__ __align__(16) char dynsmem[];
    const uint32_t sbase = smem_u32(dynsmem);
    const int tid = threadIdx.x;
    const int lane = tid & 31;
    const int wid = tid >> 5;
    const int wm = (wid & 1) << 6;
    const int wn = (wid >> 1) << 5;

    float acc[4][4][4];
#pragma unroll
    for (int i = 0; i < 4; i++)
#pragma unroll
        for (int j = 0; j < 4; j++)
#pragma unroll
            for (int q = 0; q < 4; q++) acc[i][j][q] = 0.f;

    const int jj = lane >> 3;
    const int l7 = lane & 7;
    const uint32_t a_off = (uint32_t)((wm + ((jj & 1) << 3) + l7) * (SLDH * 2) + ((jj >> 1) << 4));
    const uint32_t b_off = (uint32_t)((wn + ((jj >> 1) << 3) + l7) * (SLDH * 2) + ((jj & 1) << 4));

    const int r_ld = tid >> 3;
    const int c8 = tid & 7;

    const __half* Arow = A + (size_t)bM * lda;
    const __half* Brow = Wt + (size_t)bN * ldw;

#define ISSUE(c_, st_) do { \
    uint32_t sa = sbase + (st_) * STAGE_B; \
    uint32_t sb = sa + TILE_B; \
    int k0 = (c_) << 6; \
    _Pragma("unroll") \
    for (int i = 0; i < 4; i++) { \
        int r = r_ld + (i << 5); \
        uint32_t so = (uint32_t)(r * (SLDH * 2) + (c8 << 4)); \
        cpasync16(sa + so, Arow + (size_t)r * lda + k0 + (c8 << 3)); \
        cpasync16(sb + so, Brow + (size_t)r * ldw + k0 + (c8 << 3)); \
    } \
    COMMIT(); \
} while (0)

    const int nch = K >> 6;
    ISSUE(0, 0);
    if (nch > 1) ISSUE(1, 1);
    for (int c = 0; c < nch; c++) {
        if (c + 2 < nch) { ISSUE(c + 2, (c + 2) % 3); WAITG2(); }
        else if (c + 1 < nch) WAITG1();
        else WAITG0();
        __syncthreads();
        const uint32_t a_base = sbase + (c % 3) * STAGE_B;
        const uint32_t b_base = a_base + TILE_B;
#pragma unroll
        for (int ks = 0; ks < 4; ks++) {
            const uint32_t kb = (uint32_t)(ks << 5);
            uint32_t af[4][4], bf[2][4];
#pragma unroll
            for (int mf = 0; mf < 4; mf++)
                LDSM_X4(af[mf], a_base + a_off + (uint32_t)(mf * 16 * SLDH * 2) + kb);
#pragma unroll
            for (int p = 0; p < 2; p++)
                LDSM_X4(bf[p], b_base + b_off + (uint32_t)(p * 16 * SLDH * 2) + kb);
#pragma unroll
            for (int mf = 0; mf < 4; mf++)
#pragma unroll
                for (int nf = 0; nf < 4; nf++)
                    mma_f16(acc[mf][nf], af[mf], bf[nf >> 1] + ((nf & 1) << 1));
        }
        __syncthreads();
    }
#undef ISSUE

    const int r0 = bM + wm + (lane >> 2);
    const int c0 = bN + wn + ((lane & 3) << 1);
#pragma unroll
    for (int mf = 0; mf < 4; mf++) {
#pragma unroll
        for (int half = 0; half < 2; half++) {
            const int row = r0 + mf * 16 + half * 8;
#pragma unroll
            for (int nf = 0; nf < 4; nf++) {
                const int col = c0 + nf * 8;
                float2 v;
                v.x = acc[mf][nf][half * 2 + 0];
                v.y = acc[mf][nf][half * 2 + 1];
                if (bias) {
                    float2 bb = *reinterpret_cast<const float2*>(bias + col);
                    v.x += bb.x;
                    v.y += bb.y;
                }
                if (out_half) {
                    __half* Ch = reinterpret_cast<__half*>(Cv) + (size_t)row * ldc + col;
                    *reinterpret_cast<__half2*>(Ch) = __floats2half2_rn(v.x, v.y);
                } else {
                    float* Cf = reinterpret_cast<float*>(Cv) + (size_t)row * ldc + col;
                    *reinterpret_cast<float2*>(Cf) = v;
                }
            }
        }
    }
}

// hyper GEMM, split-K=2
__global__ __launch_bounds__(256, 2)
void hyper_gemm() {
    const int z = blockIdx.z;
    gemm_core(g_hcat + z * 1152, 2304, g_hwT + z * 1152, 2304,
              g_hgp + (size_t)z * NB * 1024, 1024, 1152, nullptr, 0,
              blockIdx.y * 128, blockIdx.x * 128);
}

// z_b GEMM: z = hhat1 @ zweight_b (half out, no bias)
__global__ __launch_bounds__(256, 2)
void z_gemm() {
    gemm_core(g_hhat1h, 256, g_zwT, 256, g_z, 256, 256, nullptr, 1,
              blockIdx.y * 128, blockIdx.x * 128);
}

// pure main GEMM (no modulation, no bias): gates_pre = [h0|x] @ weight (fp16 out)
__global__ __launch_bounds__(256, 2)
void main_pure() {
    gemm_core(g_hcat + 256, 2304, g_wT, 2048, g_gates, 4096, 2048, nullptr, 1,
              blockIdx.y * 128, blockIdx.x * 128);
}

// ---------------- dyh*dyx scalar GEMV: one warp per batch row ----------------
__global__ __launch_bounds__(256)
void dyhx_kernel(const float* __restrict__ dw_h, const float* __restrict__ dw_x) {
    __shared__ float sW4[2 * 256 * 5];   // stride-5 padding: conflict-free
    __shared__ float sB[8];
    const int tid = threadIdx.x;
    for (int i = tid; i < 2 * 256 * 4; i += 256) {
        int sel = i >> 10, k = (i >> 2) & 255, g = i & 3;
        sW4[(sel * 256 + k) * 5 + g] = g_W4[i];
    }
    if (tid < 8) sB[tid] = g_W4b[tid];
    __syncthreads();
    const int w = tid >> 5, lane = tid & 31;
    const int b = blockIdx.x * 8 + w;
    const __half* hp = g_hhat1h + (size_t)b * 256;
    float h1[8];
#pragma unroll
    for (int j = 0; j < 8; j++) h1[j] = __half2float(hp[lane + 32 * j]);
    float s[8];
#pragma unroll
    for (int o = 0; o < 8; o++) {
        int sel = o >> 2, g = o & 3;
        float a = 0.f;
#pragma unroll
        for (int j = 0; j < 8; j++)
            a += h1[j] * sW4[(sel * 256 + lane + 32 * j) * 5 + g];
#pragma unroll
        for (int d = 16; d > 0; d >>= 1) a += __shfl_xor_sync(0xFFFFFFFF, a, d);
        s[o] = a;
    }
    if (lane == 0) {
        float dwh0 = dw_h[0], dwx0 = dw_x[0];
        float4 r;
        float* rp = &r.x;
#pragma unroll
        for (int g = 0; g < 4; g++) {
            float dyh = dwh0 * (s[g] + sB[g]);
            float dyx = dwx0 * (s[4 + g] + sB[4 + g]);
            rp[g] = dyh * dyx;
        }
        *reinterpret_cast<float4*>(g_dyhx + b * 4) = r;
    }
}

// ---------------- modulation: gates = gates*dyhx + dyb + bias (one DY chain) ----------------
__global__ __launch_bounds__(256, 2)
void mod_gates(const float* __restrict__ bias) {
    extern __shared__ __align__(16) char dynsmem[];
    const uint32_t sbase = smem_u32(dynsmem);
    const int tid = threadIdx.x;
    const int lane = tid & 31;
    const int wid = tid >> 5;
    const int wm = (wid & 1) << 6;
    const int wn = (wid >> 1) << 5;
    const int bM = blockIdx.y * 128;
    const int bN = blockIdx.x * 128;
    const int g = bN >> 10;
    const int hcol = bN & 1023;

    const int jj = lane >> 3;
    const int l7 = lane & 7;
    const uint32_t a_off = (uint32_t)((wm + ((jj & 1) << 3) + l7) * (SLDH * 2) + ((jj >> 1) << 4));
    const uint32_t b_off = (uint32_t)((wn + ((jj >> 1) << 3) + l7) * (SLDH * 2) + ((jj & 1) << 4));

    const int r0 = bM + wm + (lane >> 2);
    const int c0 = bN + wn + ((lane & 3) << 1);

    // issue z_b / dw_b stage load
    {
        const __half* zp = g_z + (size_t)bM * 256 + g * 64;
        const __half* dp = g_dwT + (size_t)g * 65536 + (size_t)hcol * 64;
        uint32_t sa = sbase;
        uint32_t sb = sbase + TILE_B;
#pragma unroll
        for (int i = 0; i < 4; i++) {
            int idx = tid + (i << 8);
            int r = idx >> 3, ch = idx & 7;
            uint32_t so = (uint32_t)(r * (SLDH * 2) + (ch << 4));
            cpasync16(sa + so, zp + (size_t)r * 256 + (ch << 3));
            cpasync16(sb + so, dp + r * 64 + (ch << 3));
        }
        COMMIT();
    }

    // load pre-gates tile, scale by per-row dyhx scalar (overlaps cp.async)
    float acc[4][4][4];
#pragma unroll
    for (int mf = 0; mf < 4; mf++) {
#pragma unroll
        for (int half = 0; half < 2; half++) {
            const int row = r0 + mf * 16 + half * 8;
            const float s = g_dyhx[row * 4 + g];
            const __half* Ch = g_gates + (size_t)row * 4096;
#pragma unroll
            for (int nf = 0; nf < 4; nf++) {
                float2 v = __half22float2(*reinterpret_cast<const __half2*>(Ch + c0 + nf * 8));
                acc[mf][nf][half * 2 + 0] = v.x * s;
                acc[mf][nf][half * 2 + 1] = v.y * s;
            }
        }
    }

    WAITG0();
    __syncthreads();

    // one K=64 chain: acc += z_b @ dw_b
#pragma unroll
    for (int np = 0; np < 2; np++) {
        float dacc[4][2][4];
#pragma unroll
        for (int mf = 0; mf < 4; mf++)
#pragma unroll
            for (int j = 0; j < 2; j++)
#pragma unroll
                for (int q = 0; q < 4; q++) dacc[mf][j][q] = 0.f;
#pragma unroll
        for (int ks = 0; ks < 4; ks++) {
            const uint32_t kb = (uint32_t)(ks << 5);
            uint32_t af[4][4], bf[4];
#pragma unroll
            for (int mf = 0; mf < 4; mf++)
                LDSM_X4(af[mf], sbase + a_off + (uint32_t)(mf * 16 * SLDH * 2) + kb);
            LDSM_X4(bf, sbase + TILE_B + b_off + (uint32_t)(np * 16 * SLDH * 2) + kb);
#pragma unroll
            for (int mf = 0; mf < 4; mf++)
#pragma unroll
                for (int j = 0; j < 2; j++)
                    mma_f16(dacc[mf][j], af[mf], bf + (j << 1));
        }
#pragma unroll
        for (int mf = 0; mf < 4; mf++)
#pragma unroll
            for (int j = 0; j < 2; j++)
#pragma unroll
                for (int q = 0; q < 4; q++)
                    acc[mf][np * 2 + j][q] += dacc[mf][j][q];
    }

    // write modulated gates (+bias) as fp16
#pragma unroll
    for (int mf = 0; mf < 4; mf++) {
#pragma unroll
        for (int half = 0; half < 2; half++) {
            const int row = r0 + mf * 16 + half * 8;
            __half* Ch = g_gates + (size_t)row * 4096;
#pragma unroll
            for (int nf = 0; nf < 4; nf++) {
                const int col = c0 + nf * 8;
                float vx = acc[mf][nf][half * 2 + 0] + bias[col];
                float vy = acc[mf][nf][half * 2 + 1] + bias[col + 1];
                *reinterpret_cast<__half2*>(Ch + col) = __floats2half2_rn(vx, vy);
            }
        }
    }
}

// ---------------- elementwise cells (vectorized x4, fast activations) ----------------
__global__ void hyper_cell(const float4* __restrict__ chat0,
                           const float4* __restrict__ hbias,
                           float4* __restrict__ out_hhat1,
                           float4* __restrict__ out_chat1) {
    int idx = blockIdx.x * blockDim.x + threadIdx.x;
    if (idx >= NB * NZ / 4) return;
    int b = idx >> 6;
    int z4 = idx & 63;
    const float4* p0 = reinterpret_cast<const float4*>(g_hgp + (size_t)b * 1024);
    const float4* p1 = reinterpret_cast<const float4*>(g_hgp + (size_t)NB * 1024 + (size_t)b * 1024);
    float4 i0 = p0[z4],       i1 = p1[z4],       bi = hbias[z4];
    float4 g0 = p0[64 + z4],  g1 = p1[64 + z4],  bg = hbias[64 + z4];
    float4 f0 = p0[128 + z4], f1 = p1[128 + z4], bf = hbias[128 + z4];
    float4 o0 = p0[192 + z4], o1 = p1[192 + z4], bo = hbias[192 + z4];
    float4 cc = chat0[idx];
    float4 c1v, h1v;
    {
        float* ip0 = &i0.x; float* ip1 = &i1.x; float* bip = &bi.x;
        float* gp0 = &g0.x; float* gp1 = &g1.x; float* bgp = &bg.x;
        float* fp0 = &f0.x; float* fp1 = &f1.x; float* bfp = &bf.x;
        float* op0 = &o0.x; float* op1 = &o1.x; float* bop = &bo.x;
        float* ccp = &cc.x; float* c1p = &c1v.x; float* h1p = &h1v.x;
        __half h4[4];
#pragma unroll
        for (int q = 0; q < 4; q++) {
            float iv = ip0[q] + ip1[q] + bip[q];
            float gv = gp0[q] + gp1[q] + bgp[q];
            float fv = fp0[q] + fp1[q] + bfp[q];
            float ov = op0[q] + op1[q] + bop[q];
            float c1 = sigf(fv) * ccp[q] + sigf(iv) * tanh_fast(gv);
            float h1 = sigf(ov) * tanh_fast(c1);
            c1p[q] = c1;
            h1p[q] = h1;
            h4[q] = __float2half_rn(h1);
        }
        out_chat1[idx] = c1v;
        out_hhat1[idx] = h1v;
        *reinterpret_cast<uint2*>(g_hhat1h + idx * 4) = *reinterpret_cast<uint2*>(h4);
    }
}

__global__ void main_cell(const float4* __restrict__ c0,
                          float4* __restrict__ out_h1,
                          float4* __restrict__ out_c1) {
    int idx = blockIdx.x * blockDim.x + threadIdx.x;
    if (idx >= NB * NH / 4) return;
    int b = idx >> 8;
    int h4i = idx & 255;
    const __half* row = g_gates + (size_t)b * 4096;
    uint2 ui = *reinterpret_cast<const uint2*>(row + h4i * 4);
    uint2 ug = *reinterpret_cast<const uint2*>(row + 1024 + h4i * 4);
    uint2 uf = *reinterpret_cast<const uint2*>(row + 2048 + h4i * 4);
    uint2 uo = *reinterpret_cast<const uint2*>(row + 3072 + h4i * 4);
    float2 ia = __half22float2(*reinterpret_cast<__half2*>(&ui.x));
    float2 ib = __half22float2(*reinterpret_cast<__half2*>(&ui.y));
    float2 ga = __half22float2(*reinterpret_cast<__half2*>(&ug.x));
    float2 gb = __half22float2(*reinterpret_cast<__half2*>(&ug.y));
    float2 fa = __half22float2(*reinterpret_cast<__half2*>(&uf.x));
    float2 fb = __half22float2(*reinterpret_cast<__half2*>(&uf.y));
    float2 oa = __half22float2(*reinterpret_cast<__half2*>(&uo.x));
    float2 ob = __half22float2(*reinterpret_cast<__half2*>(&uo.y));
    float iv[4] = {ia.x, ia.y, ib.x, ib.y};
    float gv[4] = {ga.x, ga.y, gb.x, gb.y};
    float fv[4] = {fa.x, fa.y, fb.x, fb.y};
    float ov[4] = {oa.x, oa.y, ob.x, ob.y};
    float4 cc = c0[idx];
    float* ccp = &cc.x;
    float4 c1v, h1v;
    float* c1p = &c1v.x;
    float* h1p = &h1v.x;
#pragma unroll
    for (int q = 0; q < 4; q++) {
        float c1 = sigf(fv[q]) * ccp[q] + sigf(iv[q]) * tanh_fast(gv[q]);
        c1p[q] = c1;
        h1p[q] = sigf(ov[q]) * tanh_fast(c1);
    }
    out_c1[idx] = c1v;
    out_h1[idx] = h1v;
}

// ---------------- launch ----------------
extern "C" void kernel_launch(void* const* d_in, const int* in_sizes, int n_in,
                              void* d_out, int out_size) {
    const float* x       = (const float*)d_in[0];
    const float* h0      = (const float*)d_in[1];
    const float* c0      = (const float*)d_in[2];
    const float* hhat0   = (const float*)d_in[3];
    const float* chat0   = (const float*)d_in[4];
    const float* hweight = (const float*)d_in[5];
    const float* hbias   = (const float*)d_in[6];
    const float* zw_h    = (const float*)d_in[7];
    const float* zw_x    = (const float*)d_in[8];
    const float* zw_b    = (const float*)d_in[9];
    const float* zb_h    = (const float*)d_in[10];
    const float* zb_x    = (const float*)d_in[11];
    const float* dw_h    = (const float*)d_in[12];
    const float* dw_x    = (const float*)d_in[13];
    const float* dw_b    = (const float*)d_in[14];
    const float* weight  = (const float*)d_in[15];
    const float* bias    = (const float*)d_in[16];
    float* out = (float*)d_out;

    static cudaStream_t s2 = nullptr;
    static cudaEvent_t ev_fork = nullptr, ev_prep = nullptr, ev_main = nullptr;
    if (!s2) {
        cudaStreamCreateWithFlags(&s2, cudaStreamNonBlocking);
        cudaEventCreateWithFlags(&ev_fork, cudaEventDisableTiming);
        cudaEventCreateWithFlags(&ev_prep, cudaEventDisableTiming);
        cudaEventCreateWithFlags(&ev_main, cudaEventDisableTiming);
        cudaFuncSetAttribute(hyper_gemm, cudaFuncAttributeMaxDynamicSharedMemorySize, SMEM_TOT);
        cudaFuncSetAttribute(z_gemm, cudaFuncAttributeMaxDynamicSharedMemorySize, SMEM_TOT);
        cudaFuncSetAttribute(main_pure, cudaFuncAttributeMaxDynamicSharedMemorySize, SMEM_TOT);
        cudaFuncSetAttribute(mod_gates, cudaFuncAttributeMaxDynamicSharedMemorySize, SMEM_TOT);
    }

    float* out_h1    = out;
    float* out_c1    = out + (size_t)NB * NH;
    float* out_hhat1 = out + (size_t)2 * NB * NH;
    float* out_chat1 = out + (size_t)2 * NB * NH + (size_t)NB * NZ;

    // fork side stream: wT + dwT transposes
    cudaEventRecord(ev_fork, 0);
    cudaStreamWaitEvent(s2, ev_fork, 0);
    prep_side<<<8448, 256, 0, s2>>>(weight, dw_b);

    // critical path (stream 0)
    prep_main<<<3394, 256>>>((const float4*)x, (const float4*)h0, (const float4*)hhat0,
                             hweight, zw_h, zw_x, zw_b, zb_h, zb_x);
    cudaEventRecord(ev_prep, 0);

    // side stream: main GEMM mainloop overlaps the whole hyper chain
    cudaStreamWaitEvent(s2, ev_prep, 0);
    main_pure<<<dim3(32, 16), 256, SMEM_TOT, s2>>>();
    cudaEventRecord(ev_main, s2);

    // hyper chain (stream 0)
    hyper_gemm<<<dim3(8, 16, 2), 256, SMEM_TOT>>>();
    hyper_cell<<<(NB * NZ / 4) / 256, 256>>>((const float4*)chat0, (const float4*)hbias,
                                             (float4*)out_hhat1, (float4*)out_chat1);
    dyhx_kernel<<<NB / 8, 256>>>(dw_h, dw_x);
    z_gemm<<<dim3(2, 16), 256, SMEM_TOT>>>();

    // join: modulation needs z + dyhx (stream 0) and gates (side stream)
    cudaStreamWaitEvent(0, ev_main, 0);
    mod_gates<<<dim3(32, 16), 256, SMEM_TOT>>>(bias);
    main_cell<<<(NB * NH / 4) / 256, 256>>>((const float4*)c0, (float4*)out_h1, (float4*)out_c1);
}

// round 15
// speedup vs baseline: 1.0670x; 1.0670x over previous
#include <cuda_runtime.h>
#include <cuda_fp16.h>
#include <cstdint>
#include <math.h>

// Problem dims
#define NB 2048
#define ND 1024
#define NH 1024
#define NZ 256
#define NE 64

// ---------------- scratch (static device globals; no allocation) ----------------
__device__ __align__(16) __half g_hcat[NB * (NZ + NH + ND)];  // [B,2304]; cols 256.. = [h0|x]
__device__ __align__(16) float  g_hgp[2 * NB * 4 * NZ];       // split-K partials
__device__ __align__(16) __half g_hhat1h[NB * NZ];            // [B,256]
__device__ __align__(16) __half g_z[NB * 3 * 4 * NE];         // [B,768] = [z_h|z_x|z_b]
__device__ __align__(16) float  g_zbcat[768];
__device__ __align__(16) __half g_hwT[1024 * 2304];           // [N,K]
__device__ __align__(16) __half g_wT[4096 * 2048];            // [N,K]
__device__ __align__(16) __half g_zwT[768 * 256];             // [N,K]
__device__ __align__(16) __half g_dwT[12 * 1024 * 64];        // [w*4+g][N=1024][K=64]
__device__ __align__(16) __half g_gates[NB * 4 * NH];         // fp16 gates

// fast activations
__device__ __forceinline__ float sigf(float v) {
    return __fdividef(1.f, 1.f + __expf(-v));
}
__device__ __forceinline__ float tanh_fast(float x) {
    return 1.f - __fdividef(2.f, __expf(2.f * x) + 1.f);
}

__device__ __forceinline__ uint32_t smem_u32(const void* p) {
    uint32_t a;
    asm("{ .reg .u64 t; cvta.to.shared.u64 t, %1; cvt.u32.u64 %0, t; }" : "=r"(a) : "l"(p));
    return a;
}
__device__ __forceinline__ void cpasync16(uint32_t saddr, const void* gaddr) {
    asm volatile("cp.async.cg.shared.global [%0], [%1], 16;" :: "r"(saddr), "l"(gaddr));
}
#define COMMIT() asm volatile("cp.async.commit_group;" ::: "memory")
#define WAITG0() asm volatile("cp.async.wait_group 0;" ::: "memory")
#define WAITG1() asm volatile("cp.async.wait_group 1;" ::: "memory")
#define WAITG2() asm volatile("cp.async.wait_group 2;" ::: "memory")

#define LDSM_X4(r, addr) \
    asm volatile("ldmatrix.sync.aligned.m8n8.x4.shared.b16 {%0,%1,%2,%3}, [%4];" \
        : "=r"((r)[0]), "=r"((r)[1]), "=r"((r)[2]), "=r"((r)[3]) : "r"(addr))

__device__ __forceinline__ void mma_f16(float* d, const uint32_t* a, const uint32_t* b) {
    asm volatile("mma.sync.aligned.m16n8k16.row.col.f32.f16.f16.f32 "
                 "{%0,%1,%2,%3}, {%4,%5,%6,%7}, {%8,%9}, {%0,%1,%2,%3};"
                 : "+f"(d[0]), "+f"(d[1]), "+f"(d[2]), "+f"(d[3])
                 : "r"(a[0]), "r"(a[1]), "r"(a[2]), "r"(a[3]), "r"(b[0]), "r"(b[1]));
}

__device__ __forceinline__ uint2 f4_to_h4(float4 v) {
    __half2 a = __floats2half2_rn(v.x, v.y);
    __half2 b = __floats2half2_rn(v.z, v.w);
    uint2 r;
    r.x = *reinterpret_cast<uint32_t*>(&a);
    r.y = *reinterpret_cast<uint32_t*>(&b);
    return r;
}

// ---------------- transpose helper (32x32 tile, f32 in -> f16 out [N,K]) ----------------
__device__ __forceinline__ void transpose_tile(const float* __restrict__ in,
                                               __half* __restrict__ out,
                                               int K, int N, int lt, float* tbuf) {
    float (*t)[33] = reinterpret_cast<float(*)[33]>(tbuf);
    const int ntx = N >> 5;
    const int tx = lt % ntx, ty = lt / ntx;
    const int lx = threadIdx.x & 31, ly = threadIdx.x >> 5;
#pragma unroll
    for (int j = 0; j < 4; j++) {
        int k = ly + j * 8;
        t[k][lx] = in[(size_t)(ty * 32 + k) * N + tx * 32 + lx];
    }
    __syncthreads();
#pragma unroll
    for (int j = 0; j < 4; j++) {
        int r = ly + j * 8;
        out[(size_t)(tx * 32 + r) * K + ty * 32 + lx] = __float2half_rn(t[lx][r]);
    }
}

// ---------------- concat only (gates main_pure): hcat + zbcat ----------------
__global__ __launch_bounds__(256)
void concat_k(const float4* __restrict__ x, const float4* __restrict__ h0,
              const float4* __restrict__ hhat0,
              const float* __restrict__ zb_h, const float* __restrict__ zb_x) {
    uint2* hc = reinterpret_cast<uint2*>(g_hcat);
    const int HC4 = (NZ + NH + ND) / 4;  // 576
    const int N1 = NB * HC4;
    const int stride = 1024 * 256;
    const int t0 = blockIdx.x * 256 + threadIdx.x;
    for (int i = t0; i < N1; i += stride) {
        int b = i / HC4;
        int c = i - b * HC4;
        float4 v;
        if (c < NZ / 4)                 v = hhat0[b * (NZ / 4) + c];
        else if (c < (NZ + NH) / 4)     v = h0[b * (NH / 4) + (c - NZ / 4)];
        else                            v = x[b * (ND / 4) + (c - (NZ + NH) / 4)];
        hc[i] = f4_to_h4(v);
    }
    for (int i = t0; i < 768; i += stride)
        g_zbcat[i] = (i < 256) ? zb_h[i] : (i < 512) ? zb_x[i - 256] : 0.f;
}

// ---------------- hwT transpose (stream 0, overlaps main_pure) ----------------
__global__ __launch_bounds__(256)
void hwT_k(const float* __restrict__ hw) {
    __shared__ float tbuf[32 * 33];
    transpose_tile(hw, g_hwT, 2304, 1024, blockIdx.x, tbuf);
}

// ---------------- prep (side): wT + dwT + zwT transposes ----------------
__global__ __launch_bounds__(256)
void prep_side(const float* __restrict__ w,
               const float* __restrict__ dh, const float* __restrict__ dx,
               const float* __restrict__ db,
               const float* __restrict__ zh, const float* __restrict__ zx,
               const float* __restrict__ zb) {
    __shared__ float tbuf[32 * 33];
    int b2 = blockIdx.x;
    if (b2 < 8192) {
        transpose_tile(w, g_wT, 2048, 4096, b2, tbuf);
    } else if (b2 < 8960) {
        int i = (b2 - 8192) >> 6;      // 0..11
        int wsel = i / 4, g = i & 3;
        const float* in = (wsel == 0 ? dh : wsel == 1 ? dx : db) + (size_t)g * 64 * 1024;
        transpose_tile(in, g_dwT + (size_t)i * 1024 * 64, 64, 1024, (b2 - 8192) & 63, tbuf);
    } else {
        int lt = b2 - 8960;            // 0..191
        int i = lt >> 6;               // 0..2 (zw_h, zw_x, zw_b)
        const float* in = (i == 0 ? zh : i == 1 ? zx : zb);
        transpose_tile(in, g_zwT + i * 256 * 256, 256, 256, lt & 63, tbuf);
    }
}

// ---------------- shared GEMM geometry ----------------
#define SLDH 72                       // smem row stride in halfs (144B)
#define TILE_B (128 * SLDH * 2)       // 18432 bytes per operand tile
#define STAGE_B (2 * TILE_B)          // 36864 per stage
#define SMEM_TOT (3 * STAGE_B)        // 110592, 3 stages

// ---------------- fp16 GEMM core: 128x128 tile, BK=64, 3-stage ----------------
__device__ __forceinline__ void gemm_core(
    const __half* __restrict__ A, int lda,
    const __half* __restrict__ Wt, int ldw,
    void* __restrict__ Cv, int ldc, int K,
    const float* __restrict__ bias, int out_half,
    int bM, int bN) {
    extern __shared__ __align__(16) char dynsmem[];
    const uint32_t sbase = smem_u32(dynsmem);
    const int tid = threadIdx.x;
    const int lane = tid & 31;
    const int wid = tid >> 5;
    const int wm = (wid & 1) << 6;
    const int wn = (wid >> 1) << 5;

    float acc[4][4][4];
#pragma unroll
    for (int i = 0; i < 4; i++)
#pragma unroll
        for (int j = 0; j < 4; j++)
#pragma unroll
            for (int q = 0; q < 4; q++) acc[i][j][q] = 0.f;

    const int jj = lane >> 3;
    const int l7 = lane & 7;
    const uint32_t a_off = (uint32_t)((wm + ((jj & 1) << 3) + l7) * (SLDH * 2) + ((jj >> 1) << 4));
    const uint32_t b_off = (uint32_t)((wn + ((jj >> 1) << 3) + l7) * (SLDH * 2) + ((jj & 1) << 4));

    const int r_ld = tid >> 3;
    const int c8 = tid & 7;

    const __half* Arow = A + (size_t)bM * lda;
    const __half* Brow = Wt + (size_t)bN * ldw;

#define ISSUE(c_, st_) do { \
    uint32_t sa = sbase + (st_) * STAGE_B; \
    uint32_t sb = sa + TILE_B; \
    int k0 = (c_) << 6; \
    _Pragma("unroll") \
    for (int i = 0; i < 4; i++) { \
        int r = r_ld + (i << 5); \
        uint32_t so = (uint32_t)(r * (SLDH * 2) + (c8 << 4)); \
        cpasync16(sa + so, Arow + (size_t)r * lda + k0 + (c8 << 3)); \
        cpasync16(sb + so, Brow + (size_t)r * ldw + k0 + (c8 << 3)); \
    } \
    COMMIT(); \
} while (0)

    const int nch = K >> 6;
    ISSUE(0, 0);
    if (nch > 1) ISSUE(1, 1);
    for (int c = 0; c < nch; c++) {
        if (c + 2 < nch) { ISSUE(c + 2, (c + 2) % 3); WAITG2(); }
        else if (c + 1 < nch) WAITG1();
        else WAITG0();
        __syncthreads();
        const uint32_t a_base = sbase + (c % 3) * STAGE_B;
        const uint32_t b_base = a_base + TILE_B;
#pragma unroll
        for (int ks = 0; ks < 4; ks++) {
            const uint32_t kb = (uint32_t)(ks << 5);
            uint32_t af[4][4], bf[2][4];
#pragma unroll
            for (int mf = 0; mf < 4; mf++)
                LDSM_X4(af[mf], a_base + a_off + (uint32_t)(mf * 16 * SLDH * 2) + kb);
#pragma unroll
            for (int p = 0; p < 2; p++)
                LDSM_X4(bf[p], b_base + b_off + (uint32_t)(p * 16 * SLDH * 2) + kb);
#pragma unroll
            for (int mf = 0; mf < 4; mf++)
#pragma unroll
                for (int nf = 0; nf < 4; nf++)
                    mma_f16(acc[mf][nf], af[mf], bf[nf >> 1] + ((nf & 1) << 1));
        }
        __syncthreads();
    }
#undef ISSUE

    const int r0 = bM + wm + (lane >> 2);
    const int c0 = bN + wn + ((lane & 3) << 1);
#pragma unroll
    for (int mf = 0; mf < 4; mf++) {
#pragma unroll
        for (int half = 0; half < 2; half++) {
            const int row = r0 + mf * 16 + half * 8;
#pragma unroll
            for (int nf = 0; nf < 4; nf++) {
                const int col = c0 + nf * 8;
                float2 v;
                v.x = acc[mf][nf][half * 2 + 0];
                v.y = acc[mf][nf][half * 2 + 1];
                if (bias) {
                    float2 bb = *reinterpret_cast<const float2*>(bias + col);
                    v.x += bb.x;
                    v.y += bb.y;
                }
                if (out_half) {
                    __half* Ch = reinterpret_cast<__half*>(Cv) + (size_t)row * ldc + col;
                    *reinterpret_cast<__half2*>(Ch) = __floats2half2_rn(v.x, v.y);
                } else {
                    float* Cf = reinterpret_cast<float*>(Cv) + (size_t)row * ldc + col;
                    *reinterpret_cast<float2*>(Cf) = v;
                }
            }
        }
    }
}

// hyper GEMM, split-K=2
__global__ __launch_bounds__(256, 2)
void hyper_gemm() {
    const int z = blockIdx.z;
    gemm_core(g_hcat + z * 1152, 2304, g_hwT + z * 1152, 2304,
              g_hgp + (size_t)z * NB * 1024, 1024, 1152, nullptr, 0,
              blockIdx.y * 128, blockIdx.x * 128);
}

// fused z GEMM: z = hhat1 @ zw_cat + zb_cat (half out)
__global__ __launch_bounds__(256, 2)
void z_gemm() {
    gemm_core(g_hhat1h, 256, g_zwT, 256, g_z, 768, 256, g_zbcat, 1,
              blockIdx.y * 128, blockIdx.x * 128);
}

// pure main GEMM (no modulation, no bias): gates_pre = [h0|x] @ weight (fp16 out)
__global__ __launch_bounds__(256, 2)
void main_pure() {
    gemm_core(g_hcat + 256, 2304, g_wT, 2048, g_gates, 4096, 2048, nullptr, 1,
              blockIdx.y * 128, blockIdx.x * 128);
}

// ---------------- modulation kernel: gates = gates*dyh*dyx + dyb + bias ----------------
__global__ __launch_bounds__(256, 2)
void mod_gates(const float* __restrict__ bias) {
    extern __shared__ __align__(16) char dynsmem[];
    const uint32_t sbase = smem_u32(dynsmem);
    const int tid = threadIdx.x;
    const int lane = tid & 31;
    const int wid = tid >> 5;
    const int wm = (wid & 1) << 6;
    const int wn = (wid >> 1) << 5;
    const int bM = blockIdx.y * 128;
    const int bN = blockIdx.x * 128;
    const int g = bN >> 10;
    const int hcol = bN & 1023;

    const int jj = lane >> 3;
    const int l7 = lane & 7;
    const uint32_t a_off = (uint32_t)((wm + ((jj & 1) << 3) + l7) * (SLDH * 2) + ((jj >> 1) << 4));
    const uint32_t b_off = (uint32_t)((wn + ((jj >> 1) << 3) + l7) * (SLDH * 2) + ((jj & 1) << 4));

    const int r0 = bM + wm + (lane >> 2);
    const int c0 = bN + wn + ((lane & 3) << 1);

    const __half* zb0 = g_z + (size_t)bM * 768 + g * 64;
    const __half* dw0 = g_dwT + (size_t)g * 65536 + (size_t)hcol * 64;

#define ISSUE_DY(t_, st_) do { \
    const __half* zp = zb0 + (t_) * 256; \
    const __half* dp = dw0 + (size_t)(t_) * 4 * 65536; \
    uint32_t sa = sbase + (st_) * STAGE_B; \
    uint32_t sb = sa + TILE_B; \
    _Pragma("unroll") \
    for (int i = 0; i < 4; i++) { \
        int idx = tid + (i << 8); \
        int r = idx >> 3, ch = idx & 7; \
        uint32_t so = (uint32_t)(r * (SLDH * 2) + (ch << 4)); \
        cpasync16(sa + so, zp + (size_t)r * 768 + (ch << 3)); \
        cpasync16(sb + so, dp + r * 64 + (ch << 3)); \
    } \
    COMMIT(); \
} while (0)

    ISSUE_DY(0, 0);
    ISSUE_DY(1, 1);
    ISSUE_DY(2, 2);

    // load pre-modulation gates tile into acc (overlaps with cp.async)
    float acc[4][4][4];
#pragma unroll
    for (int mf = 0; mf < 4; mf++) {
#pragma unroll
        for (int half = 0; half < 2; half++) {
            const int row = r0 + mf * 16 + half * 8;
            const __half* Ch = g_gates + (size_t)row * 4096;
#pragma unroll
            for (int nf = 0; nf < 4; nf++) {
                float2 v = __half22float2(*reinterpret_cast<const __half2*>(Ch + c0 + nf * 8));
                acc[mf][nf][half * 2 + 0] = v.x;
                acc[mf][nf][half * 2 + 1] = v.y;
            }
        }
    }

#define DY_CHAIN(st_, is_add_) do { \
    const uint32_t a_base = sbase + (st_) * STAGE_B; \
    const uint32_t b_base = a_base + TILE_B; \
    _Pragma("unroll") \
    for (int np = 0; np < 2; np++) { \
        float dacc[4][2][4]; \
        _Pragma("unroll") \
        for (int mf = 0; mf < 4; mf++) \
            _Pragma("unroll") \
            for (int j = 0; j < 2; j++) \
                _Pragma("unroll") \
                for (int q = 0; q < 4; q++) dacc[mf][j][q] = 0.f; \
        _Pragma("unroll") \
        for (int ks = 0; ks < 4; ks++) { \
            const uint32_t kb = (uint32_t)(ks << 5); \
            uint32_t af[4][4], bf[4]; \
            _Pragma("unroll") \
            for (int mf = 0; mf < 4; mf++) \
                LDSM_X4(af[mf], a_base + a_off + (uint32_t)(mf * 16 * SLDH * 2) + kb); \
            LDSM_X4(bf, b_base + b_off + (uint32_t)(np * 16 * SLDH * 2) + kb); \
            _Pragma("unroll") \
            for (int mf = 0; mf < 4; mf++) \
                _Pragma("unroll") \
                for (int j = 0; j < 2; j++) \
                    mma_f16(dacc[mf][j], af[mf], bf + (j << 1)); \
        } \
        _Pragma("unroll") \
        for (int mf = 0; mf < 4; mf++) \
            _Pragma("unroll") \
            for (int j = 0; j < 2; j++) \
                _Pragma("unroll") \
                for (int q = 0; q < 4; q++) { \
                    if (is_add_) acc[mf][np * 2 + j][q] += dacc[mf][j][q]; \
                    else         acc[mf][np * 2 + j][q] *= dacc[mf][j][q]; \
                } \
    } \
} while (0)

    WAITG2();
    __syncthreads();
    DY_CHAIN(0, 0);          // acc *= dyh
    WAITG1();
    __syncthreads();
    DY_CHAIN(1, 0);          // acc *= dyx
    WAITG0();
    __syncthreads();
    DY_CHAIN(2, 1);          // acc += dyb
#undef ISSUE_DY
#undef DY_CHAIN

    // write modulated gates (+bias) back as fp16
#pragma unroll
    for (int mf = 0; mf < 4; mf++) {
#pragma unroll
        for (int half = 0; half < 2; half++) {
            const int row = r0 + mf * 16 + half * 8;
            __half* Ch = g_gates + (size_t)row * 4096;
#pragma unroll
            for (int nf = 0; nf < 4; nf++) {
                const int col = c0 + nf * 8;
                float vx = acc[mf][nf][half * 2 + 0] + bias[col];
                float vy = acc[mf][nf][half * 2 + 1] + bias[col + 1];
                *reinterpret_cast<__half2*>(Ch + col) = __floats2half2_rn(vx, vy);
            }
        }
    }
}

// ---------------- elementwise cells (vectorized x4, fast activations) ----------------
__global__ void hyper_cell(const float4* __restrict__ chat0,
                           const float4* __restrict__ hbias,
                           float4* __restrict__ out_hhat1,
                           float4* __restrict__ out_chat1) {
    int idx = blockIdx.x * blockDim.x + threadIdx.x;
    if (idx >= NB * NZ / 4) return;
    int b = idx >> 6;
    int z4 = idx & 63;
    const float4* p0 = reinterpret_cast<const float4*>(g_hgp + (size_t)b * 1024);
    const float4* p1 = reinterpret_cast<const float4*>(g_hgp + (size_t)NB * 1024 + (size_t)b * 1024);
    float4 i0 = p0[z4],       i1 = p1[z4],       bi = hbias[z4];
    float4 g0 = p0[64 + z4],  g1 = p1[64 + z4],  bg = hbias[64 + z4];
    float4 f0 = p0[128 + z4], f1 = p1[128 + z4], bf = hbias[128 + z4];
    float4 o0 = p0[192 + z4], o1 = p1[192 + z4], bo = hbias[192 + z4];
    float4 cc = chat0[idx];
    float4 c1v, h1v;
    {
        float* ip0 = &i0.x; float* ip1 = &i1.x; float* bip = &bi.x;
        float* gp0 = &g0.x; float* gp1 = &g1.x; float* bgp = &bg.x;
        float* fp0 = &f0.x; float* fp1 = &f1.x; float* bfp = &bf.x;
        float* op0 = &o0.x; float* op1 = &o1.x; float* bop = &bo.x;
        float* ccp = &cc.x; float* c1p = &c1v.x; float* h1p = &h1v.x;
        __half h4[4];
#pragma unroll
        for (int q = 0; q < 4; q++) {
            float iv = ip0[q] + ip1[q] + bip[q];
            float gv = gp0[q] + gp1[q] + bgp[q];
            float fv = fp0[q] + fp1[q] + bfp[q];
            float ov = op0[q] + op1[q] + bop[q];
            float c1 = sigf(fv) * ccp[q] + sigf(iv) * tanh_fast(gv);
            float h1 = sigf(ov) * tanh_fast(c1);
            c1p[q] = c1;
            h1p[q] = h1;
            h4[q] = __float2half_rn(h1);
        }
        out_chat1[idx] = c1v;
        out_hhat1[idx] = h1v;
        *reinterpret_cast<uint2*>(g_hhat1h + idx * 4) = *reinterpret_cast<uint2*>(h4);
    }
}

__global__ void main_cell(const float4* __restrict__ c0,
                          float4* __restrict__ out_h1,
                          float4* __restrict__ out_c1) {
    int idx = blockIdx.x * blockDim.x + threadIdx.x;
    if (idx >= NB * NH / 4) return;
    int b = idx >> 8;
    int h4i = idx & 255;
    const __half* row = g_gates + (size_t)b * 4096;
    uint2 ui = *reinterpret_cast<const uint2*>(row + h4i * 4);
    uint2 ug = *reinterpret_cast<const uint2*>(row + 1024 + h4i * 4);
    uint2 uf = *reinterpret_cast<const uint2*>(row + 2048 + h4i * 4);
    uint2 uo = *reinterpret_cast<const uint2*>(row + 3072 + h4i * 4);
    float2 ia = __half22float2(*reinterpret_cast<__half2*>(&ui.x));
    float2 ib = __half22float2(*reinterpret_cast<__half2*>(&ui.y));
    float2 ga = __half22float2(*reinterpret_cast<__half2*>(&ug.x));
    float2 gb = __half22float2(*reinterpret_cast<__half2*>(&ug.y));
    float2 fa = __half22float2(*reinterpret_cast<__half2*>(&uf.x));
    float2 fb = __half22float2(*reinterpret_cast<__half2*>(&uf.y));
    float2 oa = __half22float2(*reinterpret_cast<__half2*>(&uo.x));
    float2 ob = __half22float2(*reinterpret_cast<__half2*>(&uo.y));
    float iv[4] = {ia.x, ia.y, ib.x, ib.y};
    float gv[4] = {ga.x, ga.y, gb.x, gb.y};
    float fv[4] = {fa.x, fa.y, fb.x, fb.y};
    float ov[4] = {oa.x, oa.y, ob.x, ob.y};
    float4 cc = c0[idx];
    float* ccp = &cc.x;
    float4 c1v, h1v;
    float* c1p = &c1v.x;
    float* h1p = &h1v.x;
#pragma unroll
    for (int q = 0; q < 4; q++) {
        float c1 = sigf(fv[q]) * ccp[q] + sigf(iv[q]) * tanh_fast(gv[q]);
        c1p[q] = c1;
        h1p[q] = sigf(ov[q]) * tanh_fast(c1);
    }
    out_c1[idx] = c1v;
    out_h1[idx] = h1v;
}

// ---------------- launch ----------------
extern "C" void kernel_launch(void* const* d_in, const int* in_sizes, int n_in,
                              void* d_out, int out_size) {
    const float* x       = (const float*)d_in[0];
    const float* h0      = (const float*)d_in[1];
    const float* c0      = (const float*)d_in[2];
    const float* hhat0   = (const float*)d_in[3];
    const float* chat0   = (const float*)d_in[4];
    const float* hweight = (const float*)d_in[5];
    const float* hbias   = (const float*)d_in[6];
    const float* zw_h    = (const float*)d_in[7];
    const float* zw_x    = (const float*)d_in[8];
    const float* zw_b    = (const float*)d_in[9];
    const float* zb_h    = (const float*)d_in[10];
    const float* zb_x    = (const float*)d_in[11];
    const float* dw_h    = (const float*)d_in[12];
    const float* dw_x    = (const float*)d_in[13];
    const float* dw_b    = (const float*)d_in[14];
    const float* weight  = (const float*)d_in[15];
    const float* bias    = (const float*)d_in[16];
    float* out = (float*)d_out;

    static cudaStream_t s2 = nullptr;
    static cudaEvent_t ev_fork = nullptr, ev_concat = nullptr, ev_side = nullptr, ev_main = nullptr;
    if (!s2) {
        cudaStreamCreateWithFlags(&s2, cudaStreamNonBlocking);
        cudaEventCreateWithFlags(&ev_fork, cudaEventDisableTiming);
        cudaEventCreateWithFlags(&ev_concat, cudaEventDisableTiming);
        cudaEventCreateWithFlags(&ev_side, cudaEventDisableTiming);
        cudaEventCreateWithFlags(&ev_main, cudaEventDisableTiming);
        cudaFuncSetAttribute(hyper_gemm, cudaFuncAttributeMaxDynamicSharedMemorySize, SMEM_TOT);
        cudaFuncSetAttribute(z_gemm, cudaFuncAttributeMaxDynamicSharedMemorySize, SMEM_TOT);
        cudaFuncSetAttribute(main_pure, cudaFuncAttributeMaxDynamicSharedMemorySize, SMEM_TOT);
        cudaFuncSetAttribute(mod_gates, cudaFuncAttributeMaxDynamicSharedMemorySize, SMEM_TOT);
    }

    float* out_h1    = out;
    float* out_c1    = out + (size_t)NB * NH;
    float* out_hhat1 = out + (size_t)2 * NB * NH;
    float* out_chat1 = out + (size_t)2 * NB * NH + (size_t)NB * NZ;

    // side stream: wT + dwT + zwT transposes (independent of concat)
    cudaEventRecord(ev_fork, 0);
    cudaStreamWaitEvent(s2, ev_fork, 0);
    prep_side<<<9152, 256, 0, s2>>>(weight, dw_h, dw_x, dw_b, zw_h, zw_x, zw_b);
    cudaEventRecord(ev_side, s2);

    // stream 0: concat first (the only prep main_pure needs besides wT)
    concat_k<<<1024, 256>>>((const float4*)x, (const float4*)h0, (const float4*)hhat0,
                            zb_h, zb_x);
    cudaEventRecord(ev_concat, 0);

    // side stream: main GEMM starts as soon as wT + concat are ready
    cudaStreamWaitEvent(s2, ev_concat, 0);
    main_pure<<<dim3(32, 16), 256, SMEM_TOT, s2>>>();
    cudaEventRecord(ev_main, s2);

    // stream 0: hwT transpose overlaps main_pure, then the hyper chain
    hwT_k<<<2304, 256>>>(hweight);
    hyper_gemm<<<dim3(8, 16, 2), 256, SMEM_TOT>>>();
    hyper_cell<<<(NB * NZ / 4) / 256, 256>>>((const float4*)chat0, (const float4*)hbias,
                                             (float4*)out_hhat1, (float4*)out_chat1);
    cudaStreamWaitEvent(0, ev_side, 0);   // zwT ready (prep_side)
    z_gemm<<<dim3(6, 16), 256, SMEM_TOT>>>();

    // join: modulation needs z (stream 0) and gates/dwT (side stream)
    cudaStreamWaitEvent(0, ev_main, 0);
    mod_gates<<<dim3(32, 16), 256, SMEM_TOT>>>(bias);
    main_cell<<<(NB * NH / 4) / 256, 256>>>((const float4*)c0, (float4*)out_h1, (float4*)out_c1);
}

// round 16
// speedup vs baseline: 1.0786x; 1.0109x over previous
#include <cuda_runtime.h>
#include <cuda_fp16.h>
#include <cstdint>
#include <math.h>

// Problem dims
#define NB 2048
#define ND 1024
#define NH 1024
#define NZ 256
#define NE 64

// ---------------- scratch (static device globals; no allocation) ----------------
__device__ __align__(16) __half g_hcat[NB * (NZ + NH + ND)];  // [B,2304]; cols 256.. = [h0|x]
__device__ __align__(16) float  g_hgp[2 * NB * 4 * NZ];       // split-K partials
__device__ __align__(16) __half g_hhat1h[NB * NZ];            // [B,256]
__device__ __align__(16) __half g_z[NB * 3 * 4 * NE];         // [B,768] = [z_h|z_x|z_b]
__device__ __align__(16) float  g_zbcat[768];
__device__ __align__(16) __half g_hwT[1024 * 2304];           // [N,K]
__device__ __align__(16) __half g_wT[4096 * 2048];            // [N,K]
__device__ __align__(16) __half g_zwT[768 * 256];             // [N,K]
__device__ __align__(16) __half g_dwT[12 * 1024 * 64];        // [w*4+g][N=1024][K=64]
__device__ __align__(16) __half g_gates[NB * 4 * NH];         // fp16 gates

// fast activations
__device__ __forceinline__ float sigf(float v) {
    return __fdividef(1.f, 1.f + __expf(-v));
}
__device__ __forceinline__ float tanh_fast(float x) {
    return 1.f - __fdividef(2.f, __expf(2.f * x) + 1.f);
}

__device__ __forceinline__ uint32_t smem_u32(const void* p) {
    uint32_t a;
    asm("{ .reg .u64 t; cvta.to.shared.u64 t, %1; cvt.u32.u64 %0, t; }" : "=r"(a) : "l"(p));
    return a;
}
__device__ __forceinline__ void cpasync16(uint32_t saddr, const void* gaddr) {
    asm volatile("cp.async.cg.shared.global [%0], [%1], 16;" :: "r"(saddr), "l"(gaddr));
}
#define COMMIT() asm volatile("cp.async.commit_group;" ::: "memory")
#define WAITG0() asm volatile("cp.async.wait_group 0;" ::: "memory")
#define WAITG1() asm volatile("cp.async.wait_group 1;" ::: "memory")
#define WAITG2() asm volatile("cp.async.wait_group 2;" ::: "memory")

#define LDSM_X4(r, addr) \
    asm volatile("ldmatrix.sync.aligned.m8n8.x4.shared.b16 {%0,%1,%2,%3}, [%4];" \
        : "=r"((r)[0]), "=r"((r)[1]), "=r"((r)[2]), "=r"((r)[3]) : "r"(addr))

__device__ __forceinline__ void mma_f16(float* d, const uint32_t* a, const uint32_t* b) {
    asm volatile("mma.sync.aligned.m16n8k16.row.col.f32.f16.f16.f32 "
                 "{%0,%1,%2,%3}, {%4,%5,%6,%7}, {%8,%9}, {%0,%1,%2,%3};"
                 : "+f"(d[0]), "+f"(d[1]), "+f"(d[2]), "+f"(d[3])
                 : "r"(a[0]), "r"(a[1]), "r"(a[2]), "r"(a[3]), "r"(b[0]), "r"(b[1]));
}

__device__ __forceinline__ uint2 f4_to_h4(float4 v) {
    __half2 a = __floats2half2_rn(v.x, v.y);
    __half2 b = __floats2half2_rn(v.z, v.w);
    uint2 r;
    r.x = *reinterpret_cast<uint32_t*>(&a);
    r.y = *reinterpret_cast<uint32_t*>(&b);
    return r;
}

// ---------------- transpose helper (32x32 tile, f32 in -> f16 out [N,K]) ----------------
__device__ __forceinline__ void transpose_tile(const float* __restrict__ in,
                                               __half* __restrict__ out,
                                               int K, int N, int lt, float* tbuf) {
    float (*t)[33] = reinterpret_cast<float(*)[33]>(tbuf);
    const int ntx = N >> 5;
    const int tx = lt % ntx, ty = lt / ntx;
    const int lx = threadIdx.x & 31, ly = threadIdx.x >> 5;
#pragma unroll
    for (int j = 0; j < 4; j++) {
        int k = ly + j * 8;
        t[k][lx] = in[(size_t)(ty * 32 + k) * N + tx * 32 + lx];
    }
    __syncthreads();
#pragma unroll
    for (int j = 0; j < 4; j++) {
        int r = ly + j * 8;
        out[(size_t)(tx * 32 + r) * K + ty * 32 + lx] = __float2half_rn(t[lx][r]);
    }
}

// ---------------- prep (critical path): concat hcat + hwT + zwT + zbcat ----------------
__global__ __launch_bounds__(256)
void prep_main(const float4* __restrict__ x, const float4* __restrict__ h0,
               const float4* __restrict__ hhat0,
               const float* __restrict__ zb_h, const float* __restrict__ zb_x,
               const float* __restrict__ hw,
               const float* __restrict__ zh, const float* __restrict__ zx,
               const float* __restrict__ zb) {
    __shared__ float tbuf[32 * 33];
    if (blockIdx.x < 1024) {
        uint2* hc = reinterpret_cast<uint2*>(g_hcat);
        const int HC4 = (NZ + NH + ND) / 4;  // 576
        const int N1 = NB * HC4;
        const int stride = 1024 * 256;
        const int t0 = blockIdx.x * 256 + threadIdx.x;
        for (int i = t0; i < N1; i += stride) {
            int b = i / HC4;
            int c = i - b * HC4;
            float4 v;
            if (c < NZ / 4)                 v = hhat0[b * (NZ / 4) + c];
            else if (c < (NZ + NH) / 4)     v = h0[b * (NH / 4) + (c - NZ / 4)];
            else                            v = x[b * (ND / 4) + (c - (NZ + NH) / 4)];
            hc[i] = f4_to_h4(v);
        }
        for (int i = t0; i < 768; i += stride)
            g_zbcat[i] = (i < 256) ? zb_h[i] : (i < 512) ? zb_x[i - 256] : 0.f;
        return;
    }
    int b2 = blockIdx.x - 1024;
    if (b2 < 2304) {
        transpose_tile(hw, g_hwT, 2304, 1024, b2, tbuf);
    } else {
        int lt = b2 - 2304;            // 0..191
        int i = lt >> 6;               // 0..2 (zw_h, zw_x, zw_b)
        const float* in = (i == 0 ? zh : i == 1 ? zx : zb);
        transpose_tile(in, g_zwT + i * 256 * 256, 256, 256, lt & 63, tbuf);
    }
}

// ---------------- prep (side branch): wT + dwT transposes ----------------
__global__ __launch_bounds__(256)
void prep_side(const float* __restrict__ w,
               const float* __restrict__ dh, const float* __restrict__ dx,
               const float* __restrict__ db) {
    __shared__ float tbuf[32 * 33];
    int b2 = blockIdx.x;
    if (b2 < 8192) {
        transpose_tile(w, g_wT, 2048, 4096, b2, tbuf);
    } else {
        int i = (b2 - 8192) >> 6;      // 0..11
        int wsel = i / 4, g = i & 3;
        const float* in = (wsel == 0 ? dh : wsel == 1 ? dx : db) + (size_t)g * 64 * 1024;
        transpose_tile(in, g_dwT + (size_t)i * 1024 * 64, 64, 1024, (b2 - 8192) & 63, tbuf);
    }
}

// ---------------- shared GEMM geometry ----------------
#define SLDH 72                       // smem row stride in halfs (144B)
#define TILE_B (128 * SLDH * 2)       // 18432 bytes per operand tile
#define STAGE_B (2 * TILE_B)          // 36864 per stage
#define SMEM_TOT (3 * STAGE_B)        // 110592, 3 stages

// ---------------- fp16 GEMM core: 128x128 tile, BK=64, 3-stage ----------------
__device__ __forceinline__ void gemm_core(
    const __half* __restrict__ A, int lda,
    const __half* __restrict__ Wt, int ldw,
    void* __restrict__ Cv, int ldc, int K,
    const float* __restrict__ bias, int out_half,
    int bM, int bN) {
    extern __shared__ __align__(16) char dynsmem[];
    const uint32_t sbase = smem_u32(dynsmem);
    const int tid = threadIdx.x;
    const int lane = tid & 31;
    const int wid = tid >> 5;
    const int wm = (wid & 1) << 6;
    const int wn = (wid >> 1) << 5;

    float acc[4][4][4];
#pragma unroll
    for (int i = 0; i < 4; i++)
#pragma unroll
        for (int j = 0; j < 4; j++)
#pragma unroll
            for (int q = 0; q < 4; q++) acc[i][j][q] = 0.f;

    const int jj = lane >> 3;
    const int l7 = lane & 7;
    const uint32_t a_off = (uint32_t)((wm + ((jj & 1) << 3) + l7) * (SLDH * 2) + ((jj >> 1) << 4));
    const uint32_t b_off = (uint32_t)((wn + ((jj >> 1) << 3) + l7) * (SLDH * 2) + ((jj & 1) << 4));

    const int r_ld = tid >> 3;
    const int c8 = tid & 7;

    const __half* Arow = A + (size_t)bM * lda;
    const __half* Brow = Wt + (size_t)bN * ldw;

#define ISSUE(c_, st_) do { \
    uint32_t sa = sbase + (st_) * STAGE_B; \
    uint32_t sb = sa + TILE_B; \
    int k0 = (c_) << 6; \
    _Pragma("unroll") \
    for (int i = 0; i < 4; i++) { \
        int r = r_ld + (i << 5); \
        uint32_t so = (uint32_t)(r * (SLDH * 2) + (c8 << 4)); \
        cpasync16(sa + so, Arow + (size_t)r * lda + k0 + (c8 << 3)); \
        cpasync16(sb + so, Brow + (size_t)r * ldw + k0 + (c8 << 3)); \
    } \
    COMMIT(); \
} while (0)

    const int nch = K >> 6;
    ISSUE(0, 0);
    if (nch > 1) ISSUE(1, 1);
    for (int c = 0; c < nch; c++) {
        if (c + 2 < nch) { ISSUE(c + 2, (c + 2) % 3); WAITG2(); }
        else if (c + 1 < nch) WAITG1();
        else WAITG0();
        __syncthreads();
        const uint32_t a_base = sbase + (c % 3) * STAGE_B;
        const uint32_t b_base = a_base + TILE_B;
#pragma unroll
        for (int ks = 0; ks < 4; ks++) {
            const uint32_t kb = (uint32_t)(ks << 5);
            uint32_t af[4][4], bf[2][4];
#pragma unroll
            for (int mf = 0; mf < 4; mf++)
                LDSM_X4(af[mf], a_base + a_off + (uint32_t)(mf * 16 * SLDH * 2) + kb);
#pragma unroll
            for (int p = 0; p < 2; p++)
                LDSM_X4(bf[p], b_base + b_off + (uint32_t)(p * 16 * SLDH * 2) + kb);
#pragma unroll
            for (int mf = 0; mf < 4; mf++)
#pragma unroll
                for (int nf = 0; nf < 4; nf++)
                    mma_f16(acc[mf][nf], af[mf], bf[nf >> 1] + ((nf & 1) << 1));
        }
        __syncthreads();
    }
#undef ISSUE

    const int r0 = bM + wm + (lane >> 2);
    const int c0 = bN + wn + ((lane & 3) << 1);
#pragma unroll
    for (int mf = 0; mf < 4; mf++) {
#pragma unroll
        for (int half = 0; half < 2; half++) {
            const int row = r0 + mf * 16 + half * 8;
#pragma unroll
            for (int nf = 0; nf < 4; nf++) {
                const int col = c0 + nf * 8;
                float2 v;
                v.x = acc[mf][nf][half * 2 + 0];
                v.y = acc[mf][nf][half * 2 + 1];
                if (bias) {
                    float2 bb = *reinterpret_cast<const float2*>(bias + col);
                    v.x += bb.x;
                    v.y += bb.y;
                }
                if (out_half) {
                    __half* Ch = reinterpret_cast<__half*>(Cv) + (size_t)row * ldc + col;
                    *reinterpret_cast<__half2*>(Ch) = __floats2half2_rn(v.x, v.y);
                } else {
                    float* Cf = reinterpret_cast<float*>(Cv) + (size_t)row * ldc + col;
                    *reinterpret_cast<float2*>(Cf) = v;
                }
            }
        }
    }
}

// hyper GEMM, split-K=2
__global__ __launch_bounds__(256, 2)
void hyper_gemm() {
    const int z = blockIdx.z;
    gemm_core(g_hcat + z * 1152, 2304, g_hwT + z * 1152, 2304,
              g_hgp + (size_t)z * NB * 1024, 1024, 1152, nullptr, 0,
              blockIdx.y * 128, blockIdx.x * 128);
}

// fused z GEMM: z = hhat1 @ zw_cat + zb_cat (half out)
__global__ __launch_bounds__(256, 2)
void z_gemm() {
    gemm_core(g_hhat1h, 256, g_zwT, 256, g_z, 768, 256, g_zbcat, 1,
              blockIdx.y * 128, blockIdx.x * 128);
}

// pure main GEMM half (no modulation, no bias): gates_pre = [h0|x] @ weight (fp16 out)
__global__ __launch_bounds__(256, 2)
void main_pure(int bMoff) {
    gemm_core(g_hcat + 256, 2304, g_wT, 2048, g_gates, 4096, 2048, nullptr, 1,
              bMoff + blockIdx.y * 128, blockIdx.x * 128);
}

// ---------------- modulation kernel half: gates = gates*dyh*dyx + dyb + bias ----------------
__global__ __launch_bounds__(256, 2)
void mod_gates(const float* __restrict__ bias, int bMoff) {
    extern __shared__ __align__(16) char dynsmem[];
    const uint32_t sbase = smem_u32(dynsmem);
    const int tid = threadIdx.x;
    const int lane = tid & 31;
    const int wid = tid >> 5;
    const int wm = (wid & 1) << 6;
    const int wn = (wid >> 1) << 5;
    const int bM = bMoff + blockIdx.y * 128;
    const int bN = blockIdx.x * 128;
    const int g = bN >> 10;
    const int hcol = bN & 1023;

    const int jj = lane >> 3;
    const int l7 = lane & 7;
    const uint32_t a_off = (uint32_t)((wm + ((jj & 1) << 3) + l7) * (SLDH * 2) + ((jj >> 1) << 4));
    const uint32_t b_off = (uint32_t)((wn + ((jj >> 1) << 3) + l7) * (SLDH * 2) + ((jj & 1) << 4));

    const int r0 = bM + wm + (lane >> 2);
    const int c0 = bN + wn + ((lane & 3) << 1);

    const __half* zb0 = g_z + (size_t)bM * 768 + g * 64;
    const __half* dw0 = g_dwT + (size_t)g * 65536 + (size_t)hcol * 64;

#define ISSUE_DY(t_, st_) do { \
    const __half* zp = zb0 + (t_) * 256; \
    const __half* dp = dw0 + (size_t)(t_) * 4 * 65536; \
    uint32_t sa = sbase + (st_) * STAGE_B; \
    uint32_t sb = sa + TILE_B; \
    _Pragma("unroll") \
    for (int i = 0; i < 4; i++) { \
        int idx = tid + (i << 8); \
        int r = idx >> 3, ch = idx & 7; \
        uint32_t so = (uint32_t)(r * (SLDH * 2) + (ch << 4)); \
        cpasync16(sa + so, zp + (size_t)r * 768 + (ch << 3)); \
        cpasync16(sb + so, dp + r * 64 + (ch << 3)); \
    } \
    COMMIT(); \
} while (0)

    ISSUE_DY(0, 0);
    ISSUE_DY(1, 1);
    ISSUE_DY(2, 2);

    // load pre-modulation gates tile into acc (overlaps with cp.async)
    float acc[4][4][4];
#pragma unroll
    for (int mf = 0; mf < 4; mf++) {
#pragma unroll
        for (int half = 0; half < 2; half++) {
            const int row = r0 + mf * 16 + half * 8;
            const __half* Ch = g_gates + (size_t)row * 4096;
#pragma unroll
            for (int nf = 0; nf < 4; nf++) {
                float2 v = __half22float2(*reinterpret_cast<const __half2*>(Ch + c0 + nf * 8));
                acc[mf][nf][half * 2 + 0] = v.x;
                acc[mf][nf][half * 2 + 1] = v.y;
            }
        }
    }

#define DY_CHAIN(st_, is_add_) do { \
    const uint32_t a_base = sbase + (st_) * STAGE_B; \
    const uint32_t b_base = a_base + TILE_B; \
    _Pragma("unroll") \
    for (int np = 0; np < 2; np++) { \
        float dacc[4][2][4]; \
        _Pragma("unroll") \
        for (int mf = 0; mf < 4; mf++) \
            _Pragma("unroll") \
            for (int j = 0; j < 2; j++) \
                _Pragma("unroll") \
                for (int q = 0; q < 4; q++) dacc[mf][j][q] = 0.f; \
        _Pragma("unroll") \
        for (int ks = 0; ks < 4; ks++) { \
            const uint32_t kb = (uint32_t)(ks << 5); \
            uint32_t af[4][4], bf[4]; \
            _Pragma("unroll") \
            for (int mf = 0; mf < 4; mf++) \
                LDSM_X4(af[mf], a_base + a_off + (uint32_t)(mf * 16 * SLDH * 2) + kb); \
            LDSM_X4(bf, b_base + b_off + (uint32_t)(np * 16 * SLDH * 2) + kb); \
            _Pragma("unroll") \
            for (int mf = 0; mf < 4; mf++) \
                _Pragma("unroll") \
                for (int j = 0; j < 2; j++) \
                    mma_f16(dacc[mf][j], af[mf], bf + (j << 1)); \
        } \
        _Pragma("unroll") \
        for (int mf = 0; mf < 4; mf++) \
            _Pragma("unroll") \
            for (int j = 0; j < 2; j++) \
                _Pragma("unroll") \
                for (int q = 0; q < 4; q++) { \
                    if (is_add_) acc[mf][np * 2 + j][q] += dacc[mf][j][q]; \
                    else         acc[mf][np * 2 + j][q] *= dacc[mf][j][q]; \
                } \
    } \
} while (0)

    WAITG2();
    __syncthreads();
    DY_CHAIN(0, 0);          // acc *= dyh
    WAITG1();
    __syncthreads();
    DY_CHAIN(1, 0);          // acc *= dyx
    WAITG0();
    __syncthreads();
    DY_CHAIN(2, 1);          // acc += dyb
#undef ISSUE_DY
#undef DY_CHAIN

    // write modulated gates (+bias) back as fp16
#pragma unroll
    for (int mf = 0; mf < 4; mf++) {
#pragma unroll
        for (int half = 0; half < 2; half++) {
            const int row = r0 + mf * 16 + half * 8;
            __half* Ch = g_gates + (size_t)row * 4096;
#pragma unroll
            for (int nf = 0; nf < 4; nf++) {
                const int col = c0 + nf * 8;
                float vx = acc[mf][nf][half * 2 + 0] + bias[col];
                float vy = acc[mf][nf][half * 2 + 1] + bias[col + 1];
                *reinterpret_cast<__half2*>(Ch + col) = __floats2half2_rn(vx, vy);
            }
        }
    }
}

// ---------------- elementwise cells (vectorized x4, fast activations) ----------------
__global__ void hyper_cell(const float4* __restrict__ chat0,
                           const float4* __restrict__ hbias,
                           float4* __restrict__ out_hhat1,
                           float4* __restrict__ out_chat1) {
    int idx = blockIdx.x * blockDim.x + threadIdx.x;
    if (idx >= NB * NZ / 4) return;
    int b = idx >> 6;
    int z4 = idx & 63;
    const float4* p0 = reinterpret_cast<const float4*>(g_hgp + (size_t)b * 1024);
    const float4* p1 = reinterpret_cast<const float4*>(g_hgp + (size_t)NB * 1024 + (size_t)b * 1024);
    float4 i0 = p0[z4],       i1 = p1[z4],       bi = hbias[z4];
    float4 g0 = p0[64 + z4],  g1 = p1[64 + z4],  bg = hbias[64 + z4];
    float4 f0 = p0[128 + z4], f1 = p1[128 + z4], bf = hbias[128 + z4];
    float4 o0 = p0[192 + z4], o1 = p1[192 + z4], bo = hbias[192 + z4];
    float4 cc = chat0[idx];
    float4 c1v, h1v;
    {
        float* ip0 = &i0.x; float* ip1 = &i1.x; float* bip = &bi.x;
        float* gp0 = &g0.x; float* gp1 = &g1.x; float* bgp = &bg.x;
        float* fp0 = &f0.x; float* fp1 = &f1.x; float* bfp = &bf.x;
        float* op0 = &o0.x; float* op1 = &o1.x; float* bop = &bo.x;
        float* ccp = &cc.x; float* c1p = &c1v.x; float* h1p = &h1v.x;
        __half h4[4];
#pragma unroll
        for (int q = 0; q < 4; q++) {
            float iv = ip0[q] + ip1[q] + bip[q];
            float gv = gp0[q] + gp1[q] + bgp[q];
            float fv = fp0[q] + fp1[q] + bfp[q];
            float ov = op0[q] + op1[q] + bop[q];
            float c1 = sigf(fv) * ccp[q] + sigf(iv) * tanh_fast(gv);
            float h1 = sigf(ov) * tanh_fast(c1);
            c1p[q] = c1;
            h1p[q] = h1;
            h4[q] = __float2half_rn(h1);
        }
        out_chat1[idx] = c1v;
        out_hhat1[idx] = h1v;
        *reinterpret_cast<uint2*>(g_hhat1h + idx * 4) = *reinterpret_cast<uint2*>(h4);
    }
}

__global__ void main_cell(const float4* __restrict__ c0,
                          float4* __restrict__ out_h1,
                          float4* __restrict__ out_c1, int idx0) {
    int idx = idx0 + blockIdx.x * blockDim.x + threadIdx.x;
    if (idx >= NB * NH / 4) return;
    int b = idx >> 8;
    int h4i = idx & 255;
    const __half* row = g_gates + (size_t)b * 4096;
    uint2 ui = *reinterpret_cast<const uint2*>(row + h4i * 4);
    uint2 ug = *reinterpret_cast<const uint2*>(row + 1024 + h4i * 4);
    uint2 uf = *reinterpret_cast<const uint2*>(row + 2048 + h4i * 4);
    uint2 uo = *reinterpret_cast<const uint2*>(row + 3072 + h4i * 4);
    float2 ia = __half22float2(*reinterpret_cast<__half2*>(&ui.x));
    float2 ib = __half22float2(*reinterpret_cast<__half2*>(&ui.y));
    float2 ga = __half22float2(*reinterpret_cast<__half2*>(&ug.x));
    float2 gb = __half22float2(*reinterpret_cast<__half2*>(&ug.y));
    float2 fa = __half22float2(*reinterpret_cast<__half2*>(&uf.x));
    float2 fb = __half22float2(*reinterpret_cast<__half2*>(&uf.y));
    float2 oa = __half22float2(*reinterpret_cast<__half2*>(&uo.x));
    float2 ob = __half22float2(*reinterpret_cast<__half2*>(&uo.y));
    float iv[4] = {ia.x, ia.y, ib.x, ib.y};
    float gv[4] = {ga.x, ga.y, gb.x, gb.y};
    float fv[4] = {fa.x, fa.y, fb.x, fb.y};
    float ov[4] = {oa.x, oa.y, ob.x, ob.y};
    float4 cc = c0[idx];
    float* ccp = &cc.x;
    float4 c1v, h1v;
    float* c1p = &c1v.x;
    float* h1p = &h1v.x;
#pragma unroll
    for (int q = 0; q < 4; q++) {
        float c1 = sigf(fv[q]) * ccp[q] + sigf(iv[q]) * tanh_fast(gv[q]);
        c1p[q] = c1;
        h1p[q] = sigf(ov[q]) * tanh_fast(c1);
    }
    out_c1[idx] = c1v;
    out_h1[idx] = h1v;
}

// ---------------- launch ----------------
extern "C" void kernel_launch(void* const* d_in, const int* in_sizes, int n_in,
                              void* d_out, int out_size) {
    const float* x       = (const float*)d_in[0];
    const float* h0      = (const float*)d_in[1];
    const float* c0      = (const float*)d_in[2];
    const float* hhat0   = (const float*)d_in[3];
    const float* chat0   = (const float*)d_in[4];
    const float* hweight = (const float*)d_in[5];
    const float* hbias   = (const float*)d_in[6];
    const float* zw_h    = (const float*)d_in[7];
    const float* zw_x    = (const float*)d_in[8];
    const float* zw_b    = (const float*)d_in[9];
    const float* zb_h    = (const float*)d_in[10];
    const float* zb_x    = (const float*)d_in[11];
    const float* dw_h    = (const float*)d_in[12];
    const float* dw_x    = (const float*)d_in[13];
    const float* dw_b    = (const float*)d_in[14];
    const float* weight  = (const float*)d_in[15];
    const float* bias    = (const float*)d_in[16];
    float* out = (float*)d_out;

    static cudaStream_t s2 = nullptr;
    static cudaEvent_t ev_fork = nullptr, ev_prep = nullptr, ev_lo = nullptr, ev_hi = nullptr;
    if (!s2) {
        cudaStreamCreateWithFlags(&s2, cudaStreamNonBlocking);
        cudaEventCreateWithFlags(&ev_fork, cudaEventDisableTiming);
        cudaEventCreateWithFlags(&ev_prep, cudaEventDisableTiming);
        cudaEventCreateWithFlags(&ev_lo, cudaEventDisableTiming);
        cudaEventCreateWithFlags(&ev_hi, cudaEventDisableTiming);
        cudaFuncSetAttribute(hyper_gemm, cudaFuncAttributeMaxDynamicSharedMemorySize, SMEM_TOT);
        cudaFuncSetAttribute(z_gemm, cudaFuncAttributeMaxDynamicSharedMemorySize, SMEM_TOT);
        cudaFuncSetAttribute(main_pure, cudaFuncAttributeMaxDynamicSharedMemorySize, SMEM_TOT);
        cudaFuncSetAttribute(mod_gates, cudaFuncAttributeMaxDynamicSharedMemorySize, SMEM_TOT);
    }

    float* out_h1    = out;
    float* out_c1    = out + (size_t)NB * NH;
    float* out_hhat1 = out + (size_t)2 * NB * NH;
    float* out_chat1 = out + (size_t)2 * NB * NH + (size_t)NB * NZ;

    // fork side stream: wT + dwT transposes
    cudaEventRecord(ev_fork, 0);
    cudaStreamWaitEvent(s2, ev_fork, 0);
    prep_side<<<8960, 256, 0, s2>>>(weight, dw_h, dw_x, dw_b);

    // critical path (stream 0)
    prep_main<<<3520, 256>>>((const float4*)x, (const float4*)h0, (const float4*)hhat0,
                             zb_h, zb_x, hweight, zw_h, zw_x, zw_b);
    cudaEventRecord(ev_prep, 0);

    // side stream: main GEMM in two row-halves, overlapping the hyper chain
    cudaStreamWaitEvent(s2, ev_prep, 0);
    main_pure<<<dim3(32, 8), 256, SMEM_TOT, s2>>>(0);
    cudaEventRecord(ev_lo, s2);
    main_pure<<<dim3(32, 8), 256, SMEM_TOT, s2>>>(1024);
    cudaEventRecord(ev_hi, s2);

    // hyper chain (stream 0)
    hyper_gemm<<<dim3(8, 16, 2), 256, SMEM_TOT>>>();
    hyper_cell<<<(NB * NZ / 4) / 256, 256>>>((const float4*)chat0, (const float4*)hbias,
                                             (float4*)out_hhat1, (float4*)out_chat1);
    z_gemm<<<dim3(6, 16), 256, SMEM_TOT>>>();

    // pipelined tail: modulate+cell the lo half while the hi half GEMM finishes
    cudaStreamWaitEvent(0, ev_lo, 0);
    mod_gates<<<dim3(32, 8), 256, SMEM_TOT>>>(bias, 0);
    main_cell<<<1024, 256>>>((const float4*)c0, (float4*)out_h1, (float4*)out_c1, 0);
    cudaStreamWaitEvent(0, ev_hi, 0);
    mod_gates<<<dim3(32, 8), 256, SMEM_TOT>>>(bias, 1024);
    main_cell<<<1024, 256>>>((const float4*)c0, (float4*)out_h1, (float4*)out_c1,
                             NB * NH / 8);
}

// round 17
// speedup vs baseline: 1.0998x; 1.0197x over previous
#include <cuda_runtime.h>
#include <cuda_fp16.h>
#include <cstdint>
#include <math.h>

// Problem dims
#define NB 2048
#define ND 1024
#define NH 1024
#define NZ 256
#define NE 64

// ---------------- scratch (static device globals; no allocation) ----------------
__device__ __align__(16) __half g_hcat[NB * (NZ + NH + ND)];  // [B,2304]; cols 256.. = [h0|x]
__device__ __align__(16) float  g_hgp[2 * NB * 4 * NZ];       // split-K partials
__device__ __align__(16) __half g_hhat1h[NB * NZ];            // [B,256]
__device__ __align__(16) __half g_z[NB * 3 * 4 * NE];         // [B,768] = [z_h|z_x|z_b]
__device__ __align__(16) float  g_zbcat[768];
__device__ __align__(16) __half g_hwT[1024 * 2304];           // [N,K]
__device__ __align__(16) __half g_wT[4096 * 2048];            // [N,K]
__device__ __align__(16) __half g_zwT[768 * 256];             // [N,K]
__device__ __align__(16) __half g_dwT[12 * 1024 * 64];        // [w*4+g][N=1024][K=64]
__device__ __align__(16) __half g_gates[NB * 4 * NH];         // fp16 gates

// fast activations
__device__ __forceinline__ float sigf(float v) {
    return __fdividef(1.f, 1.f + __expf(-v));
}
__device__ __forceinline__ float tanh_fast(float x) {
    return 1.f - __fdividef(2.f, __expf(2.f * x) + 1.f);
}

__device__ __forceinline__ uint32_t smem_u32(const void* p) {
    uint32_t a;
    asm("{ .reg .u64 t; cvta.to.shared.u64 t, %1; cvt.u32.u64 %0, t; }" : "=r"(a) : "l"(p));
    return a;
}
__device__ __forceinline__ void cpasync16(uint32_t saddr, const void* gaddr) {
    asm volatile("cp.async.cg.shared.global [%0], [%1], 16;" :: "r"(saddr), "l"(gaddr));
}
#define COMMIT() asm volatile("cp.async.commit_group;" ::: "memory")
#define WAITG0() asm volatile("cp.async.wait_group 0;" ::: "memory")
#define WAITG1() asm volatile("cp.async.wait_group 1;" ::: "memory")
#define WAITG2() asm volatile("cp.async.wait_group 2;" ::: "memory")

#define LDSM_X4(r, addr) \
    asm volatile("ldmatrix.sync.aligned.m8n8.x4.shared.b16 {%0,%1,%2,%3}, [%4];" \
        : "=r"((r)[0]), "=r"((r)[1]), "=r"((r)[2]), "=r"((r)[3]) : "r"(addr))

__device__ __forceinline__ void mma_f16(float* d, const uint32_t* a, const uint32_t* b) {
    asm volatile("mma.sync.aligned.m16n8k16.row.col.f32.f16.f16.f32 "
                 "{%0,%1,%2,%3}, {%4,%5,%6,%7}, {%8,%9}, {%0,%1,%2,%3};"
                 : "+f"(d[0]), "+f"(d[1]), "+f"(d[2]), "+f"(d[3])
                 : "r"(a[0]), "r"(a[1]), "r"(a[2]), "r"(a[3]), "r"(b[0]), "r"(b[1]));
}

__device__ __forceinline__ uint2 f4_to_h4(float4 v) {
    __half2 a = __floats2half2_rn(v.x, v.y);
    __half2 b = __floats2half2_rn(v.z, v.w);
    uint2 r;
    r.x = *reinterpret_cast<uint32_t*>(&a);
    r.y = *reinterpret_cast<uint32_t*>(&b);
    return r;
}

// ---------------- transpose helper (64x64 tile, f32 in -> f16 out [N,K]) ----------------
// Reads 256B rows; writes full 128B fp16 lines. 256 threads per tile.
__device__ __forceinline__ void transpose64(const float* __restrict__ in,
                                            __half* __restrict__ out,
                                            int K, int N, int lt, float* tbuf) {
    float (*t)[65] = reinterpret_cast<float(*)[65]>(tbuf);
    const int ntx = N >> 6;
    const int tx = lt % ntx, ty = lt / ntx;
    const int lx = threadIdx.x & 63, ly = threadIdx.x >> 6;   // ly 0..3
#pragma unroll
    for (int j = 0; j < 16; j++) {
        int k = ly + j * 4;
        t[k][lx] = in[(size_t)(ty * 64 + k) * N + tx * 64 + lx];
    }
    __syncthreads();
#pragma unroll
    for (int j = 0; j < 16; j++) {
        int n = ly + j * 4;
        out[(size_t)(tx * 64 + n) * K + ty * 64 + lx] = __float2half_rn(t[lx][n]);
    }
}

// ---------------- prep (critical path): concat hcat + hwT + zwT + zbcat ----------------
// blocks: [0,1024) concat | [1024,1600) hwT (576) | [1600,1648) zwT (48)
__global__ __launch_bounds__(256)
void prep_main(const float4* __restrict__ x, const float4* __restrict__ h0,
               const float4* __restrict__ hhat0,
               const float* __restrict__ zb_h, const float* __restrict__ zb_x,
               const float* __restrict__ hw,
               const float* __restrict__ zh, const float* __restrict__ zx,
               const float* __restrict__ zb) {
    __shared__ float tbuf[64 * 65];
    if (blockIdx.x < 1024) {
        uint2* hc = reinterpret_cast<uint2*>(g_hcat);
        const int HC4 = (NZ + NH + ND) / 4;  // 576
        const int N1 = NB * HC4;
        const int stride = 1024 * 256;
        const int t0 = blockIdx.x * 256 + threadIdx.x;
        for (int i = t0; i < N1; i += stride) {
            int b = i / HC4;
            int c = i - b * HC4;
            float4 v;
            if (c < NZ / 4)                 v = hhat0[b * (NZ / 4) + c];
            else if (c < (NZ + NH) / 4)     v = h0[b * (NH / 4) + (c - NZ / 4)];
            else                            v = x[b * (ND / 4) + (c - (NZ + NH) / 4)];
            hc[i] = f4_to_h4(v);
        }
        for (int i = t0; i < 768; i += stride)
            g_zbcat[i] = (i < 256) ? zb_h[i] : (i < 512) ? zb_x[i - 256] : 0.f;
        return;
    }
    int b2 = blockIdx.x - 1024;
    if (b2 < 576) {
        transpose64(hw, g_hwT, 2304, 1024, b2, tbuf);     // 36 x 16 tiles
    } else {
        int lt = b2 - 576;              // 0..47
        int i = lt >> 4;                // 0..2 (zw_h, zw_x, zw_b)
        const float* in = (i == 0 ? zh : i == 1 ? zx : zb);
        transpose64(in, g_zwT + i * 256 * 256, 256, 256, lt & 15, tbuf);  // 4x4 tiles
    }
}

// ---------------- prep (side branch): wT + dwT transposes ----------------
// blocks: [0,2048) wT | [2048,2240) dwT (12 x 16)
__global__ __launch_bounds__(256)
void prep_side(const float* __restrict__ w,
               const float* __restrict__ dh, const float* __restrict__ dx,
               const float* __restrict__ db) {
    __shared__ float tbuf[64 * 65];
    int b2 = blockIdx.x;
    if (b2 < 2048) {
        transpose64(w, g_wT, 2048, 4096, b2, tbuf);       // 32 x 64 tiles
    } else {
        int i = (b2 - 2048) >> 4;      // 0..11
        int wsel = i / 4, g = i & 3;
        const float* in = (wsel == 0 ? dh : wsel == 1 ? dx : db) + (size_t)g * 64 * 1024;
        transpose64(in, g_dwT + (size_t)i * 1024 * 64, 64, 1024, (b2 - 2048) & 15, tbuf);
    }
}

// ---------------- shared GEMM geometry ----------------
#define SLDH 72                       // smem row stride in halfs (144B)
#define TILE_B (128 * SLDH * 2)       // 18432 bytes per operand tile
#define STAGE_B (2 * TILE_B)          // 36864 per stage
#define SMEM_TOT (3 * STAGE_B)        // 110592, 3 stages

// ---------------- fp16 GEMM core: 128x128 tile, BK=64, 3-stage ----------------
__device__ __forceinline__ void gemm_core(
    const __half* __restrict__ A, int lda,
    const __half* __restrict__ Wt, int ldw,
    void* __restrict__ Cv, int ldc, int K,
    const float* __restrict__ bias, int out_half,
    int bM, int bN) {
    extern __shared__ __align__(16) char dynsmem[];
    const uint32_t sbase = smem_u32(dynsmem);
    const int tid = threadIdx.x;
    const int lane = tid & 31;
    const int wid = tid >> 5;
    const int wm = (wid & 1) << 6;
    const int wn = (wid >> 1) << 5;

    float acc[4][4][4];
#pragma unroll
    for (int i = 0; i < 4; i++)
#pragma unroll
        for (int j = 0; j < 4; j++)
#pragma unroll
            for (int q = 0; q < 4; q++) acc[i][j][q] = 0.f;

    const int jj = lane >> 3;
    const int l7 = lane & 7;
    const uint32_t a_off = (uint32_t)((wm + ((jj & 1) << 3) + l7) * (SLDH * 2) + ((jj >> 1) << 4));
    const uint32_t b_off = (uint32_t)((wn + ((jj >> 1) << 3) + l7) * (SLDH * 2) + ((jj & 1) << 4));

    const int r_ld = tid >> 3;
    const int c8 = tid & 7;

    const __half* Arow = A + (size_t)bM * lda;
    const __half* Brow = Wt + (size_t)bN * ldw;

#define ISSUE(c_, st_) do { \
    uint32_t sa = sbase + (st_) * STAGE_B; \
    uint32_t sb = sa + TILE_B; \
    int k0 = (c_) << 6; \
    _Pragma("unroll") \
    for (int i = 0; i < 4; i++) { \
        int r = r_ld + (i << 5); \
        uint32_t so = (uint32_t)(r * (SLDH * 2) + (c8 << 4)); \
        cpasync16(sa + so, Arow + (size_t)r * lda + k0 + (c8 << 3)); \
        cpasync16(sb + so, Brow + (size_t)r * ldw + k0 + (c8 << 3)); \
    } \
    COMMIT(); \
} while (0)

    const int nch = K >> 6;
    ISSUE(0, 0);
    if (nch > 1) ISSUE(1, 1);
    for (int c = 0; c < nch; c++) {
        if (c + 2 < nch) { ISSUE(c + 2, (c + 2) % 3); WAITG2(); }
        else if (c + 1 < nch) WAITG1();
        else WAITG0();
        __syncthreads();
        const uint32_t a_base = sbase + (c % 3) * STAGE_B;
        const uint32_t b_base = a_base + TILE_B;
#pragma unroll
        for (int ks = 0; ks < 4; ks++) {
            const uint32_t kb = (uint32_t)(ks << 5);
            uint32_t af[4][4], bf[2][4];
#pragma unroll
            for (int mf = 0; mf < 4; mf++)
                LDSM_X4(af[mf], a_base + a_off + (uint32_t)(mf * 16 * SLDH * 2) + kb);
#pragma unroll
            for (int p = 0; p < 2; p++)
                LDSM_X4(bf[p], b_base + b_off + (uint32_t)(p * 16 * SLDH * 2) + kb);
#pragma unroll
            for (int mf = 0; mf < 4; mf++)
#pragma unroll
                for (int nf = 0; nf < 4; nf++)
                    mma_f16(acc[mf][nf], af[mf], bf[nf >> 1] + ((nf & 1) << 1));
        }
        __syncthreads();
    }
#undef ISSUE

    const int r0 = bM + wm + (lane >> 2);
    const int c0 = bN + wn + ((lane & 3) << 1);
#pragma unroll
    for (int mf = 0; mf < 4; mf++) {
#pragma unroll
        for (int half = 0; half < 2; half++) {
            const int row = r0 + mf * 16 + half * 8;
#pragma unroll
            for (int nf = 0; nf < 4; nf++) {
                const int col = c0 + nf * 8;
                float2 v;
                v.x = acc[mf][nf][half * 2 + 0];
                v.y = acc[mf][nf][half * 2 + 1];
                if (bias) {
                    float2 bb = *reinterpret_cast<const float2*>(bias + col);
                    v.x += bb.x;
                    v.y += bb.y;
                }
                if (out_half) {
                    __half* Ch = reinterpret_cast<__half*>(Cv) + (size_t)row * ldc + col;
                    *reinterpret_cast<__half2*>(Ch) = __floats2half2_rn(v.x, v.y);
                } else {
                    float* Cf = reinterpret_cast<float*>(Cv) + (size_t)row * ldc + col;
                    *reinterpret_cast<float2*>(Cf) = v;
                }
            }
        }
    }
}

// hyper GEMM, split-K=2
__global__ __launch_bounds__(256, 2)
void hyper_gemm() {
    const int z = blockIdx.z;
    gemm_core(g_hcat + z * 1152, 2304, g_hwT + z * 1152, 2304,
              g_hgp + (size_t)z * NB * 1024, 1024, 1152, nullptr, 0,
              blockIdx.y * 128, blockIdx.x * 128);
}

// fused z GEMM: z = hhat1 @ zw_cat + zb_cat (half out)
__global__ __launch_bounds__(256, 2)
void z_gemm() {
    gemm_core(g_hhat1h, 256, g_zwT, 256, g_z, 768, 256, g_zbcat, 1,
              blockIdx.y * 128, blockIdx.x * 128);
}

// pure main GEMM half (no modulation, no bias): gates_pre = [h0|x] @ weight (fp16 out)
__global__ __launch_bounds__(256, 2)
void main_pure(int bMoff) {
    gemm_core(g_hcat + 256, 2304, g_wT, 2048, g_gates, 4096, 2048, nullptr, 1,
              bMoff + blockIdx.y * 128, blockIdx.x * 128);
}

// ---------------- modulation kernel half: gates = gates*dyh*dyx + dyb + bias ----------------
__global__ __launch_bounds__(256, 2)
void mod_gates(const float* __restrict__ bias, int bMoff) {
    extern __shared__ __align__(16) char dynsmem[];
    const uint32_t sbase = smem_u32(dynsmem);
    const int tid = threadIdx.x;
    const int lane = tid & 31;
    const int wid = tid >> 5;
    const int wm = (wid & 1) << 6;
    const int wn = (wid >> 1) << 5;
    const int bM = bMoff + blockIdx.y * 128;
    const int bN = blockIdx.x * 128;
    const int g = bN >> 10;
    const int hcol = bN & 1023;

    const int jj = lane >> 3;
    const int l7 = lane & 7;
    const uint32_t a_off = (uint32_t)((wm + ((jj & 1) << 3) + l7) * (SLDH * 2) + ((jj >> 1) << 4));
    const uint32_t b_off = (uint32_t)((wn + ((jj >> 1) << 3) + l7) * (SLDH * 2) + ((jj & 1) << 4));

    const int r0 = bM + wm + (lane >> 2);
    const int c0 = bN + wn + ((lane & 3) << 1);

    const __half* zb0 = g_z + (size_t)bM * 768 + g * 64;
    const __half* dw0 = g_dwT + (size_t)g * 65536 + (size_t)hcol * 64;

#define ISSUE_DY(t_, st_) do { \
    const __half* zp = zb0 + (t_) * 256; \
    const __half* dp = dw0 + (size_t)(t_) * 4 * 65536; \
    uint32_t sa = sbase + (st_) * STAGE_B; \
    uint32_t sb = sa + TILE_B; \
    _Pragma("unroll") \
    for (int i = 0; i < 4; i++) { \
        int idx = tid + (i << 8); \
        int r = idx >> 3, ch = idx & 7; \
        uint32_t so = (uint32_t)(r * (SLDH * 2) + (ch << 4)); \
        cpasync16(sa + so, zp + (size_t)r * 768 + (ch << 3)); \
        cpasync16(sb + so, dp + r * 64 + (ch << 3)); \
    } \
    COMMIT(); \
} while (0)

    ISSUE_DY(0, 0);
    ISSUE_DY(1, 1);
    ISSUE_DY(2, 2);

    // load pre-modulation gates tile into acc (overlaps with cp.async)
    float acc[4][4][4];
#pragma unroll
    for (int mf = 0; mf < 4; mf++) {
#pragma unroll
        for (int half = 0; half < 2; half++) {
            const int row = r0 + mf * 16 + half * 8;
            const __half* Ch = g_gates + (size_t)row * 4096;
#pragma unroll
            for (int nf = 0; nf < 4; nf++) {
                float2 v = __half22float2(*reinterpret_cast<const __half2*>(Ch + c0 + nf * 8));
                acc[mf][nf][half * 2 + 0] = v.x;
                acc[mf][nf][half * 2 + 1] = v.y;
            }
        }
    }

#define DY_CHAIN(st_, is_add_) do { \
    const uint32_t a_base = sbase + (st_) * STAGE_B; \
    const uint32_t b_base = a_base + TILE_B; \
    _Pragma("unroll") \
    for (int np = 0; np < 2; np++) { \
        float dacc[4][2][4]; \
        _Pragma("unroll") \
        for (int mf = 0; mf < 4; mf++) \
            _Pragma("unroll") \
            for (int j = 0; j < 2; j++) \
                _Pragma("unroll") \
                for (int q = 0; q < 4; q++) dacc[mf][j][q] = 0.f; \
        _Pragma("unroll") \
        for (int ks = 0; ks < 4; ks++) { \
            const uint32_t kb = (uint32_t)(ks << 5); \
            uint32_t af[4][4], bf[4]; \
            _Pragma("unroll") \
            for (int mf = 0; mf < 4; mf++) \
                LDSM_X4(af[mf], a_base + a_off + (uint32_t)(mf * 16 * SLDH * 2) + kb); \
            LDSM_X4(bf, b_base + b_off + (uint32_t)(np * 16 * SLDH * 2) + kb); \
            _Pragma("unroll") \
            for (int mf = 0; mf < 4; mf++) \
                _Pragma("unroll") \
                for (int j = 0; j < 2; j++) \
                    mma_f16(dacc[mf][j], af[mf], bf + (j << 1)); \
        } \
        _Pragma("unroll") \
        for (int mf = 0; mf < 4; mf++) \
            _Pragma("unroll") \
            for (int j = 0; j < 2; j++) \
                _Pragma("unroll") \
                for (int q = 0; q < 4; q++) { \
                    if (is_add_) acc[mf][np * 2 + j][q] += dacc[mf][j][q]; \
                    else         acc[mf][np * 2 + j][q] *= dacc[mf][j][q]; \
                } \
    } \
} while (0)

    WAITG2();
    __syncthreads();
    DY_CHAIN(0, 0);          // acc *= dyh
    WAITG1();
    __syncthreads();
    DY_CHAIN(1, 0);          // acc *= dyx
    WAITG0();
    __syncthreads();
    DY_CHAIN(2, 1);          // acc += dyb
#undef ISSUE_DY
#undef DY_CHAIN

    // write modulated gates (+bias) back as fp16
#pragma unroll
    for (int mf = 0; mf < 4; mf++) {
#pragma unroll
        for (int half = 0; half < 2; half++) {
            const int row = r0 + mf * 16 + half * 8;
            __half* Ch = g_gates + (size_t)row * 4096;
#pragma unroll
            for (int nf = 0; nf < 4; nf++) {
                const int col = c0 + nf * 8;
                float vx = acc[mf][nf][half * 2 + 0] + bias[col];
                float vy = acc[mf][nf][half * 2 + 1] + bias[col + 1];
                *reinterpret_cast<__half2*>(Ch + col) = __floats2half2_rn(vx, vy);
            }
        }
    }
}

// ---------------- elementwise cells (vectorized x4, fast activations) ----------------
__global__ void hyper_cell(const float4* __restrict__ chat0,
                           const float4* __restrict__ hbias,
                           float4* __restrict__ out_hhat1,
                           float4* __restrict__ out_chat1) {
    int idx = blockIdx.x * blockDim.x + threadIdx.x;
    if (idx >= NB * NZ / 4) return;
    int b = idx >> 6;
    int z4 = idx & 63;
    const float4* p0 = reinterpret_cast<const float4*>(g_hgp + (size_t)b * 1024);
    const float4* p1 = reinterpret_cast<const float4*>(g_hgp + (size_t)NB * 1024 + (size_t)b * 1024);
    float4 i0 = p0[z4],       i1 = p1[z4],       bi = hbias[z4];
    float4 g0 = p0[64 + z4],  g1 = p1[64 + z4],  bg = hbias[64 + z4];
    float4 f0 = p0[128 + z4], f1 = p1[128 + z4], bf = hbias[128 + z4];
    float4 o0 = p0[192 + z4], o1 = p1[192 + z4], bo = hbias[192 + z4];
    float4 cc = chat0[idx];
    float4 c1v, h1v;
    {
        float* ip0 = &i0.x; float* ip1 = &i1.x; float* bip = &bi.x;
        float* gp0 = &g0.x; float* gp1 = &g1.x; float* bgp = &bg.x;
        float* fp0 = &f0.x; float* fp1 = &f1.x; float* bfp = &bf.x;
        float* op0 = &o0.x; float* op1 = &o1.x; float* bop = &bo.x;
        float* ccp = &cc.x; float* c1p = &c1v.x; float* h1p = &h1v.x;
        __half h4[4];
#pragma unroll
        for (int q = 0; q < 4; q++) {
            float iv = ip0[q] + ip1[q] + bip[q];
            float gv = gp0[q] + gp1[q] + bgp[q];
            float fv = fp0[q] + fp1[q] + bfp[q];
            float ov = op0[q] + op1[q] + bop[q];
            float c1 = sigf(fv) * ccp[q] + sigf(iv) * tanh_fast(gv);
            float h1 = sigf(ov) * tanh_fast(c1);
            c1p[q] = c1;
            h1p[q] = h1;
            h4[q] = __float2half_rn(h1);
        }
        out_chat1[idx] = c1v;
        out_hhat1[idx] = h1v;
        *reinterpret_cast<uint2*>(g_hhat1h + idx * 4) = *reinterpret_cast<uint2*>(h4);
    }
}

__global__ void main_cell(const float4* __restrict__ c0,
                          float4* __restrict__ out_h1,
                          float4* __restrict__ out_c1, int idx0) {
    int idx = idx0 + blockIdx.x * blockDim.x + threadIdx.x;
    if (idx >= NB * NH / 4) return;
    int b = idx >> 8;
    int h4i = idx & 255;
    const __half* row = g_gates + (size_t)b * 4096;
    uint2 ui = *reinterpret_cast<const uint2*>(row + h4i * 4);
    uint2 ug = *reinterpret_cast<const uint2*>(row + 1024 + h4i * 4);
    uint2 uf = *reinterpret_cast<const uint2*>(row + 2048 + h4i * 4);
    uint2 uo = *reinterpret_cast<const uint2*>(row + 3072 + h4i * 4);
    float2 ia = __half22float2(*reinterpret_cast<__half2*>(&ui.x));
    float2 ib = __half22float2(*reinterpret_cast<__half2*>(&ui.y));
    float2 ga = __half22float2(*reinterpret_cast<__half2*>(&ug.x));
    float2 gb = __half22float2(*reinterpret_cast<__half2*>(&ug.y));
    float2 fa = __half22float2(*reinterpret_cast<__half2*>(&uf.x));
    float2 fb = __half22float2(*reinterpret_cast<__half2*>(&uf.y));
    float2 oa = __half22float2(*reinterpret_cast<__half2*>(&uo.x));
    float2 ob = __half22float2(*reinterpret_cast<__half2*>(&uo.y));
    float iv[4] = {ia.x, ia.y, ib.x, ib.y};
    float gv[4] = {ga.x, ga.y, gb.x, gb.y};
    float fv[4] = {fa.x, fa.y, fb.x, fb.y};
    float ov[4] = {oa.x, oa.y, ob.x, ob.y};
    float4 cc = c0[idx];
    float* ccp = &cc.x;
    float4 c1v, h1v;
    float* c1p = &c1v.x;
    float* h1p = &h1v.x;
#pragma unroll
    for (int q = 0; q < 4; q++) {
        float c1 = sigf(fv[q]) * ccp[q] + sigf(iv[q]) * tanh_fast(gv[q]);
        c1p[q] = c1;
        h1p[q] = sigf(ov[q]) * tanh_fast(c1);
    }
    out_c1[idx] = c1v;
    out_h1[idx] = h1v;
}

// ---------------- launch ----------------
extern "C" void kernel_launch(void* const* d_in, const int* in_sizes, int n_in,
                              void* d_out, int out_size) {
    const float* x       = (const float*)d_in[0];
    const float* h0      = (const float*)d_in[1];
    const float* c0      = (const float*)d_in[2];
    const float* hhat0   = (const float*)d_in[3];
    const float* chat0   = (const float*)d_in[4];
    const float* hweight = (const float*)d_in[5];
    const float* hbias   = (const float*)d_in[6];
    const float* zw_h    = (const float*)d_in[7];
    const float* zw_x    = (const float*)d_in[8];
    const float* zw_b    = (const float*)d_in[9];
    const float* zb_h    = (const float*)d_in[10];
    const float* zb_x    = (const float*)d_in[11];
    const float* dw_h    = (const float*)d_in[12];
    const float* dw_x    = (const float*)d_in[13];
    const float* dw_b    = (const float*)d_in[14];
    const float* weight  = (const float*)d_in[15];
    const float* bias    = (const float*)d_in[16];
    float* out = (float*)d_out;

    static cudaStream_t s2 = nullptr;
    static cudaEvent_t ev_fork = nullptr, ev_prep = nullptr, ev_lo = nullptr, ev_hi = nullptr;
    if (!s2) {
        cudaStreamCreateWithFlags(&s2, cudaStreamNonBlocking);
        cudaEventCreateWithFlags(&ev_fork, cudaEventDisableTiming);
        cudaEventCreateWithFlags(&ev_prep, cudaEventDisableTiming);
        cudaEventCreateWithFlags(&ev_lo, cudaEventDisableTiming);
        cudaEventCreateWithFlags(&ev_hi, cudaEventDisableTiming);
        cudaFuncSetAttribute(hyper_gemm, cudaFuncAttributeMaxDynamicSharedMemorySize, SMEM_TOT);
        cudaFuncSetAttribute(z_gemm, cudaFuncAttributeMaxDynamicSharedMemorySize, SMEM_TOT);
        cudaFuncSetAttribute(main_pure, cudaFuncAttributeMaxDynamicSharedMemorySize, SMEM_TOT);
        cudaFuncSetAttribute(mod_gates, cudaFuncAttributeMaxDynamicSharedMemorySize, SMEM_TOT);
    }

    float* out_h1    = out;
    float* out_c1    = out + (size_t)NB * NH;
    float* out_hhat1 = out + (size_t)2 * NB * NH;
    float* out_chat1 = out + (size_t)2 * NB * NH + (size_t)NB * NZ;

    // fork side stream: wT + dwT transposes (64x64 tiles)
    cudaEventRecord(ev_fork, 0);
    cudaStreamWaitEvent(s2, ev_fork, 0);
    prep_side<<<2240, 256, 0, s2>>>(weight, dw_h, dw_x, dw_b);

    // critical path (stream 0)
    prep_main<<<1648, 256>>>((const float4*)x, (const float4*)h0, (const float4*)hhat0,
                             zb_h, zb_x, hweight, zw_h, zw_x, zw_b);
    cudaEventRecord(ev_prep, 0);

    // side stream: main GEMM in two row-halves, overlapping the hyper chain
    cudaStreamWaitEvent(s2, ev_prep, 0);
    main_pure<<<dim3(32, 8), 256, SMEM_TOT, s2>>>(0);
    cudaEventRecord(ev_lo, s2);
    main_pure<<<dim3(32, 8), 256, SMEM_TOT, s2>>>(1024);
    cudaEventRecord(ev_hi, s2);

    // hyper chain (stream 0)
    hyper_gemm<<<dim3(8, 16, 2), 256, SMEM_TOT>>>();
    hyper_cell<<<(NB * NZ / 4) / 256, 256>>>((const float4*)chat0, (const float4*)hbias,
                                             (float4*)out_hhat1, (float4*)out_chat1);
    z_gemm<<<dim3(6, 16), 256, SMEM_TOT>>>();

    // pipelined tail: modulate+cell the lo half while the hi half GEMM finishes
    cudaStreamWaitEvent(0, ev_lo, 0);
    mod_gates<<<dim3(32, 8), 256, SMEM_TOT>>>(bias, 0);
    main_cell<<<1024, 256>>>((const float4*)c0, (float4*)out_h1, (float4*)out_c1, 0);
    cudaStreamWaitEvent(0, ev_hi, 0);
    mod_gates<<<dim3(32, 8), 256, SMEM_TOT>>>(bias, 1024);
    main_cell<<<1024, 256>>>((const float4*)c0, (float4*)out_h1, (float4*)out_c1,
                             NB * NH / 8);
}